// round 11
// baseline (speedup 1.0000x reference)
#include <cuda_runtime.h>
#include <cstdint>
#include <stdint.h>
#include <math.h>

#define NN 50000
#define EE 400000

// ---------------- scratch (device globals) ----------------
__device__ float g_y[(size_t)NN * 2048];     // q|k|v|s slices, each NN*512
__device__ float g_h[(size_t)NN * 512];
__device__ float g_hhi[(size_t)NN * 512];
__device__ float g_hlo[(size_t)NN * 512];
__device__ float g_xhi[(size_t)NN * 128];
__device__ float g_xlo[(size_t)NN * 128];
__device__ float g_w1hi[4 * 128 * 512];
__device__ float g_w1lo[4 * 128 * 512];
__device__ float g_w2hi[4 * 512 * 256];
__device__ float g_w2lo[4 * 512 * 256];
__device__ float g_alpha[(size_t)EE * 4];
__device__ int   g_rowptr[NN + 1];
__device__ int   g_cursor[NN];
__device__ int   g_perm[EE];
__device__ int   g_chunksum[256];

// ---------------- tf32 helpers ----------------
__device__ __forceinline__ uint32_t f2tf(float x) {
    uint32_t r;
    asm("cvt.rna.tf32.f32 %0, %1;" : "=r"(r) : "f"(x));
    return r;
}
__device__ __forceinline__ void mma_tf32(float* c, const uint32_t* a, const uint32_t* b) {
    asm volatile(
        "mma.sync.aligned.m16n8k8.row.col.f32.tf32.tf32.f32 "
        "{%0,%1,%2,%3}, {%4,%5,%6,%7}, {%8,%9}, {%0,%1,%2,%3};"
        : "+f"(c[0]), "+f"(c[1]), "+f"(c[2]), "+f"(c[3])
        : "r"(a[0]), "r"(a[1]), "r"(a[2]), "r"(a[3]), "r"(b[0]), "r"(b[1]));
}
__device__ __forceinline__ uint32_t s2u(const void* p) {
    return (uint32_t)__cvta_generic_to_shared(p);
}
__device__ __forceinline__ void cpa16(uint32_t dst, const void* src, int sbytes) {
    asm volatile("cp.async.ca.shared.global [%0], [%1], 16, %2;\n"
                 :: "r"(dst), "l"(src), "r"(sbytes));
}
__device__ __forceinline__ void cpa_commit() {
    asm volatile("cp.async.commit_group;\n" ::: "memory");
}

// ---------------- CSR build (by dst) ----------------
__global__ void k_zero_rowptr(int n) {
    int i = blockIdx.x * blockDim.x + threadIdx.x;
    if (i < n) g_rowptr[i] = 0;
}
__global__ void k_count(const int* __restrict__ dst, int E) {
    int e = blockIdx.x * blockDim.x + threadIdx.x;
    if (e < E) atomicAdd(&g_rowptr[dst[e] + 1], 1);
}
__global__ void k_block_sums(int n) {
    __shared__ int sh[256];
    int i = blockIdx.x * 256 + threadIdx.x;
    sh[threadIdx.x] = (i < n) ? g_rowptr[i] : 0;
    __syncthreads();
    for (int o = 128; o > 0; o >>= 1) {
        if (threadIdx.x < o) sh[threadIdx.x] += sh[threadIdx.x + o];
        __syncthreads();
    }
    if (threadIdx.x == 0) g_chunksum[blockIdx.x] = sh[0];
}
__global__ void k_scan_chunks(int nch) {
    if (threadIdx.x == 0 && blockIdx.x == 0) {
        int running = 0;
        for (int i = 0; i < nch; i++) {
            int t = g_chunksum[i];
            g_chunksum[i] = running;
            running += t;
        }
    }
}
__global__ void k_block_scan(int n) {
    __shared__ int sh[256];
    int i = blockIdx.x * 256 + threadIdx.x;
    int t = threadIdx.x;
    sh[t] = (i < n) ? g_rowptr[i] : 0;
    __syncthreads();
    for (int o = 1; o < 256; o <<= 1) {
        int v = sh[t];
        int u = (t >= o) ? sh[t - o] : 0;
        __syncthreads();
        sh[t] = v + u;
        __syncthreads();
    }
    if (i < n) g_rowptr[i] = sh[t] + g_chunksum[blockIdx.x];
}
__global__ void k_cursor(int n) {
    int i = blockIdx.x * blockDim.x + threadIdx.x;
    if (i < n) g_cursor[i] = g_rowptr[i];
}
__global__ void k_scatter(const int* __restrict__ dst, int E) {
    int e = blockIdx.x * blockDim.x + threadIdx.x;
    if (e < E) {
        int p = atomicAdd(&g_cursor[dst[e]], 1);
        g_perm[p] = e;
    }
}

// ---------------- tf32 hi/lo split kernels ----------------
__global__ void k_split1(const float* __restrict__ W, float* __restrict__ hi,
                         float* __restrict__ lo, int n) {
    int i = blockIdx.x * blockDim.x + threadIdx.x;
    if (i >= n) return;
    float v = W[i];
    float h = __uint_as_float(f2tf(v));
    hi[i] = h;
    lo[i] = __uint_as_float(f2tf(v - h));
}
__global__ void k_split4(const float* __restrict__ W0, const float* __restrict__ W1,
                         const float* __restrict__ W2, const float* __restrict__ W3,
                         float* __restrict__ hi, float* __restrict__ lo, int n) {
    int idx = blockIdx.x * blockDim.x + threadIdx.x;
    if (idx >= 4 * n) return;
    int m = idx / n, j = idx % n;
    const float* W = m == 0 ? W0 : m == 1 ? W1 : m == 2 ? W2 : W3;
    float v = W[j];
    float h = __uint_as_float(f2tf(v));
    hi[idx] = h;
    lo[idx] = __uint_as_float(f2tf(v - h));
}

// ---------------- pipelined TF32x3 tensor-core GEMM (pre-split operands) ----------------
#define AST 36
#define BST 136
#define ASZ (128 * AST)
#define BSZ (32 * BST)
#define SST (2 * ASZ + 2 * BSZ)          // floats per stage: 17920
#define MMA_SMEM (2 * SST * 4)           // 143360 B

__global__ void __launch_bounds__(256) k_mma4(const float* __restrict__ Ahi,
                                              const float* __restrict__ Alo,
                                              const float* __restrict__ Whi,
                                              const float* __restrict__ Wlo,
                                              const float* __restrict__ b0, float* __restrict__ o0,
                                              const float* __restrict__ b1, float* __restrict__ o1,
                                              const float* __restrict__ b2, float* __restrict__ o2,
                                              const float* __restrict__ b3, float* __restrict__ o3,
                                              int M, int K, int F) {
    extern __shared__ float sm[];

    int tid = threadIdx.x;
    int warp = tid >> 5, lane = tid & 31;
    int wm = warp >> 2;
    int wn = warp & 3;
    int gid = lane >> 2;
    int l4 = lane & 3;

    int nb = F / 128;
    int bsel = blockIdx.x / nb;
    int bn = blockIdx.x % nb;
    int bm = blockIdx.y;
    const float* bias = bsel == 0 ? b0 : bsel == 1 ? b1 : bsel == 2 ? b2 : b3;
    float* outp = bsel == 0 ? o0 : bsel == 1 ? o1 : bsel == 2 ? o2 : o3;
    size_t wbase = (size_t)bsel * K * F + (size_t)bn * 128;

    // per-thread fill coordinates
    int ar_ = tid >> 3;            // A row 0..31 (+i*32)
    int afc = (tid & 7) * 4;       // A col
    int bkk = tid >> 3;            // B k-row 0..31
    int bnc = (tid & 7) * 4;       // B col (+i*32)

    float acc[4][4][4];
#pragma unroll
    for (int i = 0; i < 4; i++)
#pragma unroll
        for (int j = 0; j < 4; j++)
#pragma unroll
            for (int r = 0; r < 4; r++) acc[i][j][r] = 0.f;

    int nIter = K / 32;

    // prefetch lambda (macro-style)
#define PREFETCH(IT, BI)                                                              \
    do {                                                                              \
        float* base = sm + (BI) * SST;                                                \
        float* ah = base;                                                             \
        float* al = base + ASZ;                                                       \
        float* bh_ = base + 2 * ASZ;                                                  \
        float* bl_ = base + 2 * ASZ + BSZ;                                            \
        int k0 = (IT) * 32;                                                           \
        _Pragma("unroll")                                                             \
        for (int i = 0; i < 4; i++) {                                                 \
            int r = ar_ + i * 32;                                                     \
            int gr = bm * 128 + r;                                                    \
            int ok = (gr < M) ? 16 : 0;                                               \
            size_t off = (size_t)(gr < M ? gr : 0) * K + k0 + afc;                    \
            cpa16(s2u(ah + r * AST + afc), Ahi + off, ok);                            \
            cpa16(s2u(al + r * AST + afc), Alo + off, ok);                            \
        }                                                                             \
        {                                                                             \
            size_t woff = wbase + (size_t)(k0 + bkk) * F;                             \
            _Pragma("unroll")                                                         \
            for (int i = 0; i < 4; i++) {                                             \
                int n = bnc + i * 32;                                                 \
                cpa16(s2u(bh_ + bkk * BST + n), Whi + woff + n, 16);                  \
                cpa16(s2u(bl_ + bkk * BST + n), Wlo + woff + n, 16);                  \
            }                                                                         \
        }                                                                             \
        cpa_commit();                                                                 \
    } while (0)

    PREFETCH(0, 0);
    if (nIter > 1) PREFETCH(1, 1);

    for (int it = 0; it < nIter; it++) {
        if (it + 1 < nIter)
            asm volatile("cp.async.wait_group 1;\n" ::: "memory");
        else
            asm volatile("cp.async.wait_group 0;\n" ::: "memory");
        __syncthreads();

        int cur = it & 1;
        const float* As_hi = sm + cur * SST;
        const float* As_lo = As_hi + ASZ;
        const float* Bs_hi = As_hi + 2 * ASZ;
        const float* Bs_lo = As_hi + 2 * ASZ + BSZ;

#pragma unroll
        for (int ks = 0; ks < 32; ks += 8) {
            uint32_t ah[4][4], al[4][4], bh[4][2], bl[4][2];
#pragma unroll
            for (int tm = 0; tm < 4; tm++) {
                int m0 = wm * 64 + tm * 16 + gid;
                const float* ph = As_hi + m0 * AST + ks + l4;
                const float* pl = As_lo + m0 * AST + ks + l4;
                ah[tm][0] = __float_as_uint(ph[0]);
                ah[tm][1] = __float_as_uint(ph[8 * AST]);
                ah[tm][2] = __float_as_uint(ph[4]);
                ah[tm][3] = __float_as_uint(ph[8 * AST + 4]);
                al[tm][0] = __float_as_uint(pl[0]);
                al[tm][1] = __float_as_uint(pl[8 * AST]);
                al[tm][2] = __float_as_uint(pl[4]);
                al[tm][3] = __float_as_uint(pl[8 * AST + 4]);
            }
#pragma unroll
            for (int tn = 0; tn < 4; tn++) {
                int n0 = wn * 32 + tn * 8 + gid;
                const float* ph = Bs_hi + (ks + l4) * BST + n0;
                const float* pl = Bs_lo + (ks + l4) * BST + n0;
                bh[tn][0] = __float_as_uint(ph[0]);
                bh[tn][1] = __float_as_uint(ph[4 * BST]);
                bl[tn][0] = __float_as_uint(pl[0]);
                bl[tn][1] = __float_as_uint(pl[4 * BST]);
            }
#pragma unroll
            for (int tm = 0; tm < 4; tm++)
#pragma unroll
                for (int tn = 0; tn < 4; tn++) {
                    mma_tf32(acc[tm][tn], ah[tm], bh[tn]);
                    mma_tf32(acc[tm][tn], ah[tm], bl[tn]);
                    mma_tf32(acc[tm][tn], al[tm], bh[tn]);
                }
        }
        __syncthreads();
        if (it + 2 < nIter) PREFETCH(it + 2, cur);
    }

#pragma unroll
    for (int tm = 0; tm < 4; tm++) {
        int r0 = bm * 128 + wm * 64 + tm * 16 + gid;
        int r1 = r0 + 8;
#pragma unroll
        for (int tn = 0; tn < 4; tn++) {
            int c = bn * 128 + wn * 32 + tn * 8 + l4 * 2;
            if (r0 < M) {
                outp[(size_t)r0 * F + c] = acc[tm][tn][0] + bias[c];
                outp[(size_t)r0 * F + c + 1] = acc[tm][tn][1] + bias[c + 1];
            }
            if (r1 < M) {
                outp[(size_t)r1 * F + c] = acc[tm][tn][2] + bias[c];
                outp[(size_t)r1 * F + c + 1] = acc[tm][tn][3] + bias[c + 1];
            }
        }
    }
#undef PREFETCH
}

// ---------------- CSR dst-side score: warp per node, q cached in registers ----------------
template <int H, int C>
__global__ void k_alphaC(const int* __restrict__ src,
                         const float* __restrict__ q, const float* __restrict__ k,
                         int n, float scale) {
    constexpr int F = H * C;
    constexpr int T = F / 128;
    int node = (blockIdx.x * blockDim.x + threadIdx.x) >> 5;
    int lane = threadIdx.x & 31;
    if (node >= n) return;
    int s0 = g_rowptr[node], s1 = g_rowptr[node + 1];
    if (s0 == s1) return;

    float4 qr[T];
    const float4* qp = (const float4*)(q + (size_t)node * F);
#pragma unroll
    for (int t = 0; t < T; t++) qr[t] = qp[lane + 32 * t];

    for (int j = s0; j < s1; j++) {
        int e = g_perm[j];
        const float4* kp = (const float4*)(k + (size_t)src[e] * F);
        float acc[H];
#pragma unroll
        for (int h = 0; h < H; h++) acc[h] = 0.f;
#pragma unroll
        for (int t = 0; t < T; t++) {
            float4 a = qr[t], b = kp[lane + 32 * t];
            float d = a.x * b.x + a.y * b.y + a.z * b.z + a.w * b.w;
            if constexpr (C == 128) {
                acc[t] += d;
            } else {
                if (lane < 16) acc[2 * t] += d;
                else acc[2 * t + 1] += d;
            }
        }
#pragma unroll
        for (int h = 0; h < H; h++) {
            float v = acc[h];
#pragma unroll
            for (int o = 16; o; o >>= 1) v += __shfl_xor_sync(0xffffffffu, v, o);
            if (lane == 0) g_alpha[(size_t)e * H + h] = v * scale;
        }
    }
}

// ---------------- CSR warp-per-node agg (float4) + optional tf32-split output ----------------
template <int H, int C>
__global__ void k_aggC(const int* __restrict__ src,
                       const float* __restrict__ v, const float* __restrict__ sskip,
                       const float* __restrict__ lng, const float* __restrict__ lnb,
                       float* __restrict__ outp, float* __restrict__ ohi,
                       float* __restrict__ olo, int n) {
    constexpr int F = H * C, V = F / 128;
    int node = (blockIdx.x * blockDim.x + threadIdx.x) >> 5;
    int lane = threadIdx.x & 31;
    if (node >= n) return;
    int s0 = g_rowptr[node], s1 = g_rowptr[node + 1], deg = s1 - s0;

    float m[H], dn[H];
#pragma unroll
    for (int h = 0; h < H; h++) {
        float mv = -INFINITY;
        for (int j = lane; j < deg; j += 32)
            mv = fmaxf(mv, g_alpha[(size_t)g_perm[s0 + j] * H + h]);
#pragma unroll
        for (int o = 16; o; o >>= 1) mv = fmaxf(mv, __shfl_xor_sync(0xffffffffu, mv, o));
        m[h] = mv;
        float sv = 0.f;
        for (int j = lane; j < deg; j += 32)
            sv += __expf(g_alpha[(size_t)g_perm[s0 + j] * H + h] - mv);
#pragma unroll
        for (int o = 16; o; o >>= 1) sv += __shfl_xor_sync(0xffffffffu, sv, o);
        dn[h] = 1.f / (sv + 1e-16f);
    }

    float4 acc[V];
#pragma unroll
    for (int t = 0; t < V; t++) acc[t] = make_float4(0.f, 0.f, 0.f, 0.f);

    for (int j = 0; j < deg; j++) {
        int e = g_perm[s0 + j];
        int sv = src[e];
        float w[H];
#pragma unroll
        for (int h = 0; h < H; h++)
            w[h] = __expf(g_alpha[(size_t)e * H + h] - m[h]) * dn[h];
        const float4* vr = (const float4*)(v + (size_t)sv * F);
#pragma unroll
        for (int t = 0; t < V; t++) {
            float ww;
            if constexpr (C == 128) ww = w[t];
            else ww = (lane < 16) ? w[2 * t] : w[2 * t + 1];
            float4 b = vr[lane + 32 * t];
            acc[t].x = fmaf(ww, b.x, acc[t].x);
            acc[t].y = fmaf(ww, b.y, acc[t].y);
            acc[t].z = fmaf(ww, b.z, acc[t].z);
            acc[t].w = fmaf(ww, b.w, acc[t].w);
        }
    }
    const float4* sr = (const float4*)(sskip + (size_t)node * F);
#pragma unroll
    for (int t = 0; t < V; t++) {
        float4 b = sr[lane + 32 * t];
        acc[t].x += b.x; acc[t].y += b.y; acc[t].z += b.z; acc[t].w += b.w;
    }

    float s = 0.f;
#pragma unroll
    for (int t = 0; t < V; t++) s += acc[t].x + acc[t].y + acc[t].z + acc[t].w;
#pragma unroll
    for (int o = 16; o; o >>= 1) s += __shfl_xor_sync(0xffffffffu, s, o);
    float mean = s / (float)F;
    float vs = 0.f;
#pragma unroll
    for (int t = 0; t < V; t++) {
        float dx = acc[t].x - mean, dy = acc[t].y - mean,
              dz = acc[t].z - mean, dw = acc[t].w - mean;
        vs = fmaf(dx, dx, vs); vs = fmaf(dy, dy, vs);
        vs = fmaf(dz, dz, vs); vs = fmaf(dw, dw, vs);
    }
#pragma unroll
    for (int o = 16; o; o >>= 1) vs += __shfl_xor_sync(0xffffffffu, vs, o);
    float r = rsqrtf(vs / (float)F + 1e-5f);
    const float4* gp = (const float4*)lng;
    const float4* bp = (const float4*)lnb;
    float4* op = (float4*)(outp + (size_t)node * F);
#pragma unroll
    for (int t = 0; t < V; t++) {
        int f4 = lane + 32 * t;
        float4 g = gp[f4], bb = bp[f4], o4;
        float tx = (acc[t].x - mean) * r * g.x + bb.x;
        float ty = (acc[t].y - mean) * r * g.y + bb.y;
        float tz = (acc[t].z - mean) * r * g.z + bb.z;
        float tw = (acc[t].w - mean) * r * g.w + bb.w;
        o4.x = tx > 0.f ? tx : expm1f(tx);
        o4.y = ty > 0.f ? ty : expm1f(ty);
        o4.z = tz > 0.f ? tz : expm1f(tz);
        o4.w = tw > 0.f ? tw : expm1f(tw);
        op[f4] = o4;
        if (ohi) {
            float4 hh, ll;
            hh.x = __uint_as_float(f2tf(o4.x)); ll.x = __uint_as_float(f2tf(o4.x - hh.x));
            hh.y = __uint_as_float(f2tf(o4.y)); ll.y = __uint_as_float(f2tf(o4.y - hh.y));
            hh.z = __uint_as_float(f2tf(o4.z)); ll.z = __uint_as_float(f2tf(o4.z - hh.z));
            hh.w = __uint_as_float(f2tf(o4.w)); ll.w = __uint_as_float(f2tf(o4.w - hh.w));
            ((float4*)(ohi + (size_t)node * F))[f4] = hh;
            ((float4*)(olo + (size_t)node * F))[f4] = ll;
        }
    }
}

// ---------------- layer 3: fused projection, warp per node ----------------
__global__ void k_gemm3f(const float* __restrict__ X,
                         const float* __restrict__ Wq, const float* __restrict__ bq,
                         const float* __restrict__ Wk, const float* __restrict__ bk,
                         const float* __restrict__ Wv, const float* __restrict__ bv,
                         const float* __restrict__ Ws, const float* __restrict__ bs,
                         float* __restrict__ q, float* __restrict__ k,
                         float* __restrict__ v, float* __restrict__ sOut, int n) {
    int node = (blockIdx.x * blockDim.x + threadIdx.x) >> 5;
    int lane = threadIdx.x & 31;
    if (node >= n) return;
    const float* x = X + (size_t)node * 256;
    float a[8];
#pragma unroll
    for (int i = 0; i < 8; i++) a[i] = 0.f;
#pragma unroll
    for (int t = 0; t < 8; t++) {
        int i = lane + 32 * t;
        float xv = x[i];
        a[0] = fmaf(xv, Wq[i * 2], a[0]);
        a[1] = fmaf(xv, Wq[i * 2 + 1], a[1]);
        a[2] = fmaf(xv, Wk[i * 2], a[2]);
        a[3] = fmaf(xv, Wk[i * 2 + 1], a[3]);
        a[4] = fmaf(xv, Wv[i * 2], a[4]);
        a[5] = fmaf(xv, Wv[i * 2 + 1], a[5]);
        a[6] = fmaf(xv, Ws[i * 2], a[6]);
        a[7] = fmaf(xv, Ws[i * 2 + 1], a[7]);
    }
#pragma unroll
    for (int i = 0; i < 8; i++) {
#pragma unroll
        for (int o = 16; o; o >>= 1) a[i] += __shfl_xor_sync(0xffffffffu, a[i], o);
    }
    if (lane == 0) {
        q[(size_t)node * 2 + 0] = a[0] + bq[0];
        q[(size_t)node * 2 + 1] = a[1] + bq[1];
        k[(size_t)node * 2 + 0] = a[2] + bk[0];
        k[(size_t)node * 2 + 1] = a[3] + bk[1];
        v[(size_t)node * 2 + 0] = a[4] + bv[0];
        v[(size_t)node * 2 + 1] = a[5] + bv[1];
        sOut[(size_t)node * 2 + 0] = a[6] + bs[0];
        sOut[(size_t)node * 2 + 1] = a[7] + bs[1];
    }
}

// ---------------- layer-3 score: thread-per-edge ----------------
__global__ void k_alpha3(const int* __restrict__ src, const int* __restrict__ dst,
                         const float* __restrict__ q, const float* __restrict__ k,
                         int E, float scale) {
    int e = blockIdx.x * blockDim.x + threadIdx.x;
    if (e >= E) return;
    const float* qp = q + (size_t)dst[e] * 2;
    const float* kp = k + (size_t)src[e] * 2;
    g_alpha[e] = (qp[0] * kp[0] + qp[1] * kp[1]) * scale;
}

// ---------------- layer 3 CSR finalize ----------------
__global__ void k_final3(const int* __restrict__ src,
                         const float* __restrict__ v2, const float* __restrict__ s3,
                         float* __restrict__ out, int n) {
    int i = blockIdx.x * blockDim.x + threadIdx.x;
    if (i >= n) return;
    int s0 = g_rowptr[i], s1 = g_rowptr[i + 1];
    float m = -INFINITY;
    for (int j = s0; j < s1; j++) m = fmaxf(m, g_alpha[g_perm[j]]);
    float a0 = 0.f, a1 = 0.f;
    if (s1 > s0) {
        float dnm = 0.f;
        for (int j = s0; j < s1; j++) dnm += __expf(g_alpha[g_perm[j]] - m);
        float inv = 1.f / (dnm + 1e-16f);
        for (int j = s0; j < s1; j++) {
            int e = g_perm[j];
            float w = __expf(g_alpha[e] - m) * inv;
            const float* vr = v2 + (size_t)src[e] * 2;
            a0 = fmaf(w, vr[0], a0);
            a1 = fmaf(w, vr[1], a1);
        }
    }
    float h0 = a0 + s3[(size_t)i * 2 + 0];
    float h1 = a1 + s3[(size_t)i * 2 + 1];
    float mx = fmaxf(h0, h1);
    float lse = mx + logf(expf(h0 - mx) + expf(h1 - mx));
    out[2 * i + 0] = h0 - lse;
    out[2 * i + 1] = h1 - lse;
}

// ---------------- launch ----------------
static inline int cdiv(int a, int b) { return (a + b - 1) / b; }

extern "C" void kernel_launch(void* const* d_in, const int* in_sizes, int n_in,
                              void* d_out, int out_size) {
    const float* x = (const float*)d_in[0];
    const int* ei = (const int*)d_in[1];
    const int N = in_sizes[0] / 128;
    const int E = in_sizes[1] / 2;
    const int* src = ei;
    const int* dst = ei + E;

    const float *Wq1 = (const float*)d_in[2],  *bq1 = (const float*)d_in[3];
    const float *Wk1 = (const float*)d_in[4],  *bk1 = (const float*)d_in[5];
    const float *Wv1 = (const float*)d_in[6],  *bv1 = (const float*)d_in[7];
    const float *Ws1 = (const float*)d_in[8],  *bs1 = (const float*)d_in[9];
    const float *Wq2 = (const float*)d_in[10], *bq2 = (const float*)d_in[11];
    const float *Wk2 = (const float*)d_in[12], *bk2 = (const float*)d_in[13];
    const float *Wv2 = (const float*)d_in[14], *bv2 = (const float*)d_in[15];
    const float *Ws2 = (const float*)d_in[16], *bs2 = (const float*)d_in[17];
    const float *Wq3 = (const float*)d_in[18], *bq3 = (const float*)d_in[19];
    const float *Wk3 = (const float*)d_in[20], *bk3 = (const float*)d_in[21];
    const float *Wv3 = (const float*)d_in[22], *bv3 = (const float*)d_in[23];
    const float *Ws3 = (const float*)d_in[24], *bs3 = (const float*)d_in[25];
    const float *ln1g = (const float*)d_in[26], *ln1b = (const float*)d_in[27];
    const float *ln2g = (const float*)d_in[28], *ln2b = (const float*)d_in[29];
    float* out = (float*)d_out;

    static float *yb = nullptr, *hb = nullptr, *hhi = nullptr, *hlo = nullptr;
    static float *xhi = nullptr, *xlo = nullptr;
    static float *w1hi = nullptr, *w1lo = nullptr, *w2hi = nullptr, *w2lo = nullptr;
    static bool cfg = false;
    static cudaStream_t s2;
    static cudaEvent_t evFork, evJoin;
    if (!cfg) {
        void* p;
        cudaGetSymbolAddress(&p, g_y); yb = (float*)p;
        cudaGetSymbolAddress(&p, g_h); hb = (float*)p;
        cudaGetSymbolAddress(&p, g_hhi); hhi = (float*)p;
        cudaGetSymbolAddress(&p, g_hlo); hlo = (float*)p;
        cudaGetSymbolAddress(&p, g_xhi); xhi = (float*)p;
        cudaGetSymbolAddress(&p, g_xlo); xlo = (float*)p;
        cudaGetSymbolAddress(&p, g_w1hi); w1hi = (float*)p;
        cudaGetSymbolAddress(&p, g_w1lo); w1lo = (float*)p;
        cudaGetSymbolAddress(&p, g_w2hi); w2hi = (float*)p;
        cudaGetSymbolAddress(&p, g_w2lo); w2lo = (float*)p;
        cudaFuncSetAttribute(k_mma4, cudaFuncAttributeMaxDynamicSharedMemorySize, MMA_SMEM);
        cudaStreamCreateWithFlags(&s2, cudaStreamNonBlocking);
        cudaEventCreateWithFlags(&evFork, cudaEventDisableTiming);
        cudaEventCreateWithFlags(&evJoin, cudaEventDisableTiming);
        cfg = true;
    }

    float* q = yb;
    float* k = yb + (size_t)NN * 512;
    float* v = yb + (size_t)NN * 1024;
    float* sOut = yb + (size_t)NN * 1536;

    const int TB = 256;

    // ---- fork: CSR build + layer-2 weight split on s2 ----
    cudaEventRecord(evFork, 0);
    cudaStreamWaitEvent(s2, evFork, 0);

    int n1 = N + 1;
    int nch = cdiv(n1, 256);
    k_zero_rowptr<<<cdiv(n1, TB), TB, 0, s2>>>(n1);
    k_count<<<cdiv(E, TB), TB, 0, s2>>>(dst, E);
    k_block_sums<<<nch, 256, 0, s2>>>(n1);
    k_scan_chunks<<<1, 32, 0, s2>>>(nch);
    k_block_scan<<<nch, 256, 0, s2>>>(n1);
    k_cursor<<<cdiv(N, TB), TB, 0, s2>>>(N);
    k_scatter<<<cdiv(E, TB), TB, 0, s2>>>(dst, E);
    k_split4<<<cdiv(4 * 512 * 256, TB), TB, 0, s2>>>(Wq2, Wk2, Wv2, Ws2, w2hi, w2lo, 512 * 256);
    cudaEventRecord(evJoin, s2);

    // ---- default stream: input/weight splits for layer 1, then GEMM ----
    k_split1<<<cdiv(N * 128, TB), TB>>>(x, xhi, xlo, N * 128);
    k_split4<<<cdiv(4 * 128 * 512, TB), TB>>>(Wq1, Wk1, Wv1, Ws1, w1hi, w1lo, 128 * 512);

    // ================= layer 1: K=128, F=512, H=4, C=128 =================
    {
        int K = 128, F = 512;
        dim3 grid(4 * F / 128, cdiv(N, 128));
        k_mma4<<<grid, 256, MMA_SMEM>>>(xhi, xlo, w1hi, w1lo,
                                        bq1, q, bk1, k, bv1, v, bs1, sOut, N, K, F);
        cudaStreamWaitEvent(0, evJoin, 0);
        k_alphaC<4, 128><<<cdiv(N * 32, TB), TB>>>(src, q, k, N, 0.08838834764831845f);
        k_aggC<4, 128><<<cdiv(N * 32, TB), TB>>>(src, v, sOut, ln1g, ln1b, hb, hhi, hlo, N);
    }
    // ================= layer 2: K=512, F=256, H=4, C=64 =================
    {
        int K = 512, F = 256;
        dim3 grid(4 * F / 128, cdiv(N, 128));
        k_mma4<<<grid, 256, MMA_SMEM>>>(hhi, hlo, w2hi, w2lo,
                                        bq2, q, bk2, k, bv2, v, bs2, sOut, N, K, F);
        k_alphaC<4, 64><<<cdiv(N * 32, TB), TB>>>(src, q, k, N, 0.125f);
        k_aggC<4, 64><<<cdiv(N * 32, TB), TB>>>(src, v, sOut, ln2g, ln2b, hb, nullptr, nullptr, N);
    }
    // ================= layer 3: K=256, F=2, H=1, C=2 =================
    {
        k_gemm3f<<<cdiv(N * 32, TB), TB>>>(hb, Wq3, bq3, Wk3, bk3, Wv3, bv3, Ws3, bs3,
                                           q, k, v, sOut, N);
        k_alpha3<<<cdiv(E, TB), TB>>>(src, dst, q, k, E, 0.7071067811865475f);
        k_final3<<<cdiv(N, TB), TB>>>(src, v, sOut, out, N);
    }
}

// round 12
// speedup vs baseline: 1.0617x; 1.0617x over previous
#include <cuda_runtime.h>
#include <cstdint>
#include <stdint.h>
#include <math.h>

#define NN 50000
#define EE 400000

// ---------------- scratch (device globals) ----------------
__device__ float g_y[(size_t)NN * 2048];     // q|k|v|s slices, each NN*512
__device__ float g_h[(size_t)NN * 512];
__device__ float g_alpha[(size_t)EE * 4];
__device__ int   g_rowptr[NN + 1];
__device__ int   g_cursor[NN];
__device__ int   g_perm[EE];
__device__ int   g_chunksum[256];

// ---------------- tf32 helpers ----------------
__device__ __forceinline__ uint32_t f2tf(float x) {
    uint32_t r;
    asm("cvt.rna.tf32.f32 %0, %1;" : "=r"(r) : "f"(x));
    return r;
}
__device__ __forceinline__ void cvt2(float f, uint32_t& h, uint32_t& l) {
    h = f2tf(f);
    l = f2tf(f - __uint_as_float(h));
}
__device__ __forceinline__ void mma_tf32(float* c, const uint32_t* a, const uint32_t* b) {
    asm volatile(
        "mma.sync.aligned.m16n8k8.row.col.f32.tf32.tf32.f32 "
        "{%0,%1,%2,%3}, {%4,%5,%6,%7}, {%8,%9}, {%0,%1,%2,%3};"
        : "+f"(c[0]), "+f"(c[1]), "+f"(c[2]), "+f"(c[3])
        : "r"(a[0]), "r"(a[1]), "r"(a[2]), "r"(a[3]), "r"(b[0]), "r"(b[1]));
}
__device__ __forceinline__ uint32_t s2u(const void* p) {
    return (uint32_t)__cvta_generic_to_shared(p);
}
__device__ __forceinline__ void cpa16(uint32_t dst, const void* src, int sbytes) {
    asm volatile("cp.async.ca.shared.global [%0], [%1], 16, %2;\n"
                 :: "r"(dst), "l"(src), "r"(sbytes));
}
__device__ __forceinline__ void cpa_commit() {
    asm volatile("cp.async.commit_group;\n" ::: "memory");
}

// ---------------- CSR build (by dst) ----------------
__global__ void k_zero_rowptr(int n) {
    int i = blockIdx.x * blockDim.x + threadIdx.x;
    if (i < n) g_rowptr[i] = 0;
}
__global__ void k_count(const int* __restrict__ dst, int E) {
    int e = blockIdx.x * blockDim.x + threadIdx.x;
    if (e < E) atomicAdd(&g_rowptr[dst[e] + 1], 1);
}
__global__ void k_block_sums(int n) {
    __shared__ int sh[256];
    int i = blockIdx.x * 256 + threadIdx.x;
    sh[threadIdx.x] = (i < n) ? g_rowptr[i] : 0;
    __syncthreads();
    for (int o = 128; o > 0; o >>= 1) {
        if (threadIdx.x < o) sh[threadIdx.x] += sh[threadIdx.x + o];
        __syncthreads();
    }
    if (threadIdx.x == 0) g_chunksum[blockIdx.x] = sh[0];
}
__global__ void k_scan_chunks(int nch) {
    if (threadIdx.x == 0 && blockIdx.x == 0) {
        int running = 0;
        for (int i = 0; i < nch; i++) {
            int t = g_chunksum[i];
            g_chunksum[i] = running;
            running += t;
        }
    }
}
__global__ void k_block_scan(int n) {
    __shared__ int sh[256];
    int i = blockIdx.x * 256 + threadIdx.x;
    int t = threadIdx.x;
    sh[t] = (i < n) ? g_rowptr[i] : 0;
    __syncthreads();
    for (int o = 1; o < 256; o <<= 1) {
        int v = sh[t];
        int u = (t >= o) ? sh[t - o] : 0;
        __syncthreads();
        sh[t] = v + u;
        __syncthreads();
    }
    if (i < n) g_rowptr[i] = sh[t] + g_chunksum[blockIdx.x];
}
__global__ void k_cursor(int n) {
    int i = blockIdx.x * blockDim.x + threadIdx.x;
    if (i < n) g_cursor[i] = g_rowptr[i];
}
__global__ void k_scatter(const int* __restrict__ dst, int E) {
    int e = blockIdx.x * blockDim.x + threadIdx.x;
    if (e < E) {
        int p = atomicAdd(&g_cursor[dst[e]], 1);
        g_perm[p] = e;
    }
}

// ---------------- pipelined TF32x3 GEMM: raw-float cp.async tiles, convert at frag load ----
#define AST 36
#define BST 136
#define ASZ (128 * AST)                  // 4608 floats
#define BSZ (32 * BST)                   // 4352 floats
#define SST (ASZ + BSZ)                  // 8960 floats per stage
#define MMA_SMEM (2 * SST * 4)           // 71680 B

__global__ void __launch_bounds__(256) k_mma4(const float* __restrict__ Ag,
                                              const float* __restrict__ W0, const float* __restrict__ b0, float* __restrict__ o0,
                                              const float* __restrict__ W1, const float* __restrict__ b1, float* __restrict__ o1,
                                              const float* __restrict__ W2, const float* __restrict__ b2, float* __restrict__ o2,
                                              const float* __restrict__ W3, const float* __restrict__ b3, float* __restrict__ o3,
                                              int M, int K, int F) {
    extern __shared__ float sm[];

    int tid = threadIdx.x;
    int warp = tid >> 5, lane = tid & 31;
    int wm = warp >> 2;
    int wn = warp & 3;
    int gid = lane >> 2;
    int l4 = lane & 3;

    int nb = F / 128;
    int bsel = blockIdx.x / nb;
    int bn = blockIdx.x % nb;
    int bm = blockIdx.y;
    const float* W = bsel == 0 ? W0 : bsel == 1 ? W1 : bsel == 2 ? W2 : W3;
    const float* bias = bsel == 0 ? b0 : bsel == 1 ? b1 : bsel == 2 ? b2 : b3;
    float* outp = bsel == 0 ? o0 : bsel == 1 ? o1 : bsel == 2 ? o2 : o3;

    // fill coordinates
    int ar_ = tid >> 3;            // A row 0..31 (+i*32)
    int afc = (tid & 7) * 4;       // A col
    int bkk = tid >> 3;            // B k-row 0..31
    int bnc = (tid & 7) * 4;       // B col (+i*32)

    float acc[4][4][4];
#pragma unroll
    for (int i = 0; i < 4; i++)
#pragma unroll
        for (int j = 0; j < 4; j++)
#pragma unroll
            for (int r = 0; r < 4; r++) acc[i][j][r] = 0.f;

    int nIter = K / 32;

#define PREFETCH(IT, BI)                                                              \
    do {                                                                              \
        float* as_ = sm + (BI) * SST;                                                 \
        float* bs_ = as_ + ASZ;                                                       \
        int k0 = (IT) * 32;                                                           \
        _Pragma("unroll")                                                             \
        for (int i = 0; i < 4; i++) {                                                 \
            int r = ar_ + i * 32;                                                     \
            int gr = bm * 128 + r;                                                    \
            int ok = (gr < M) ? 16 : 0;                                               \
            size_t off = (size_t)(gr < M ? gr : 0) * K + k0 + afc;                    \
            cpa16(s2u(as_ + r * AST + afc), Ag + off, ok);                            \
        }                                                                             \
        {                                                                             \
            const float* Wrow = W + (size_t)(k0 + bkk) * F + bn * 128;                \
            _Pragma("unroll")                                                         \
            for (int i = 0; i < 4; i++) {                                             \
                int n = bnc + i * 32;                                                 \
                cpa16(s2u(bs_ + bkk * BST + n), Wrow + n, 16);                        \
            }                                                                         \
        }                                                                             \
        cpa_commit();                                                                 \
    } while (0)

    PREFETCH(0, 0);
    if (nIter > 1) PREFETCH(1, 1);

    for (int it = 0; it < nIter; it++) {
        if (it + 1 < nIter)
            asm volatile("cp.async.wait_group 1;\n" ::: "memory");
        else
            asm volatile("cp.async.wait_group 0;\n" ::: "memory");
        __syncthreads();

        int cur = it & 1;
        const float* As = sm + cur * SST;
        const float* Bs = As + ASZ;

#pragma unroll
        for (int ks = 0; ks < 32; ks += 8) {
            uint32_t ah[4][4], al[4][4], bh[4][2], bl[4][2];
#pragma unroll
            for (int tm = 0; tm < 4; tm++) {
                int m0 = wm * 64 + tm * 16 + gid;
                const float* pa = As + m0 * AST + ks + l4;
                cvt2(pa[0],             ah[tm][0], al[tm][0]);
                cvt2(pa[8 * AST],       ah[tm][1], al[tm][1]);
                cvt2(pa[4],             ah[tm][2], al[tm][2]);
                cvt2(pa[8 * AST + 4],   ah[tm][3], al[tm][3]);
            }
#pragma unroll
            for (int tn = 0; tn < 4; tn++) {
                int n0 = wn * 32 + tn * 8 + gid;
                const float* pb = Bs + (ks + l4) * BST + n0;
                cvt2(pb[0],         bh[tn][0], bl[tn][0]);
                cvt2(pb[4 * BST],   bh[tn][1], bl[tn][1]);
            }
#pragma unroll
            for (int tm = 0; tm < 4; tm++)
#pragma unroll
                for (int tn = 0; tn < 4; tn++) {
                    mma_tf32(acc[tm][tn], ah[tm], bh[tn]);
                    mma_tf32(acc[tm][tn], ah[tm], bl[tn]);
                    mma_tf32(acc[tm][tn], al[tm], bh[tn]);
                }
        }
        __syncthreads();
        if (it + 2 < nIter) PREFETCH(it + 2, cur);
    }
#undef PREFETCH

#pragma unroll
    for (int tm = 0; tm < 4; tm++) {
        int r0 = bm * 128 + wm * 64 + tm * 16 + gid;
        int r1 = r0 + 8;
#pragma unroll
        for (int tn = 0; tn < 4; tn++) {
            int c = bn * 128 + wn * 32 + tn * 8 + l4 * 2;
            if (r0 < M) {
                outp[(size_t)r0 * F + c] = acc[tm][tn][0] + bias[c];
                outp[(size_t)r0 * F + c + 1] = acc[tm][tn][1] + bias[c + 1];
            }
            if (r1 < M) {
                outp[(size_t)r1 * F + c] = acc[tm][tn][2] + bias[c];
                outp[(size_t)r1 * F + c + 1] = acc[tm][tn][3] + bias[c + 1];
            }
        }
    }
}

// ---------------- CSR dst-side score: warp per node, q cached in registers ----------------
template <int H, int C>
__global__ void k_alphaC(const int* __restrict__ src,
                         const float* __restrict__ q, const float* __restrict__ k,
                         int n, float scale) {
    constexpr int F = H * C;
    constexpr int T = F / 128;
    int node = (blockIdx.x * blockDim.x + threadIdx.x) >> 5;
    int lane = threadIdx.x & 31;
    if (node >= n) return;
    int s0 = g_rowptr[node], s1 = g_rowptr[node + 1];
    if (s0 == s1) return;

    float4 qr[T];
    const float4* qp = (const float4*)(q + (size_t)node * F);
#pragma unroll
    for (int t = 0; t < T; t++) qr[t] = qp[lane + 32 * t];

    for (int j = s0; j < s1; j++) {
        int e = g_perm[j];
        const float4* kp = (const float4*)(k + (size_t)src[e] * F);
        float acc[H];
#pragma unroll
        for (int h = 0; h < H; h++) acc[h] = 0.f;
#pragma unroll
        for (int t = 0; t < T; t++) {
            float4 a = qr[t], b = kp[lane + 32 * t];
            float d = a.x * b.x + a.y * b.y + a.z * b.z + a.w * b.w;
            if constexpr (C == 128) {
                acc[t] += d;
            } else {
                if (lane < 16) acc[2 * t] += d;
                else acc[2 * t + 1] += d;
            }
        }
#pragma unroll
        for (int h = 0; h < H; h++) {
            float v = acc[h];
#pragma unroll
            for (int o = 16; o; o >>= 1) v += __shfl_xor_sync(0xffffffffu, v, o);
            if (lane == 0) g_alpha[(size_t)e * H + h] = v * scale;
        }
    }
}

// ---------------- CSR warp-per-node agg (float4): softmax + aggregate + skip + LN + ELU ----
template <int H, int C>
__global__ void k_aggC(const int* __restrict__ src,
                       const float* __restrict__ v, const float* __restrict__ sskip,
                       const float* __restrict__ lng, const float* __restrict__ lnb,
                       float* __restrict__ outp, int n) {
    constexpr int F = H * C, V = F / 128;
    int node = (blockIdx.x * blockDim.x + threadIdx.x) >> 5;
    int lane = threadIdx.x & 31;
    if (node >= n) return;
    int s0 = g_rowptr[node], s1 = g_rowptr[node + 1], deg = s1 - s0;

    float m[H], dn[H];
#pragma unroll
    for (int h = 0; h < H; h++) {
        float mv = -INFINITY;
        for (int j = lane; j < deg; j += 32)
            mv = fmaxf(mv, g_alpha[(size_t)g_perm[s0 + j] * H + h]);
#pragma unroll
        for (int o = 16; o; o >>= 1) mv = fmaxf(mv, __shfl_xor_sync(0xffffffffu, mv, o));
        m[h] = mv;
        float sv = 0.f;
        for (int j = lane; j < deg; j += 32)
            sv += __expf(g_alpha[(size_t)g_perm[s0 + j] * H + h] - mv);
#pragma unroll
        for (int o = 16; o; o >>= 1) sv += __shfl_xor_sync(0xffffffffu, sv, o);
        dn[h] = 1.f / (sv + 1e-16f);
    }

    float4 acc[V];
#pragma unroll
    for (int t = 0; t < V; t++) acc[t] = make_float4(0.f, 0.f, 0.f, 0.f);

    for (int j = 0; j < deg; j++) {
        int e = g_perm[s0 + j];
        int sv = src[e];
        float w[H];
#pragma unroll
        for (int h = 0; h < H; h++)
            w[h] = __expf(g_alpha[(size_t)e * H + h] - m[h]) * dn[h];
        const float4* vr = (const float4*)(v + (size_t)sv * F);
#pragma unroll
        for (int t = 0; t < V; t++) {
            float ww;
            if constexpr (C == 128) ww = w[t];
            else ww = (lane < 16) ? w[2 * t] : w[2 * t + 1];
            float4 b = vr[lane + 32 * t];
            acc[t].x = fmaf(ww, b.x, acc[t].x);
            acc[t].y = fmaf(ww, b.y, acc[t].y);
            acc[t].z = fmaf(ww, b.z, acc[t].z);
            acc[t].w = fmaf(ww, b.w, acc[t].w);
        }
    }
    const float4* sr = (const float4*)(sskip + (size_t)node * F);
#pragma unroll
    for (int t = 0; t < V; t++) {
        float4 b = sr[lane + 32 * t];
        acc[t].x += b.x; acc[t].y += b.y; acc[t].z += b.z; acc[t].w += b.w;
    }

    float s = 0.f;
#pragma unroll
    for (int t = 0; t < V; t++) s += acc[t].x + acc[t].y + acc[t].z + acc[t].w;
#pragma unroll
    for (int o = 16; o; o >>= 1) s += __shfl_xor_sync(0xffffffffu, s, o);
    float mean = s / (float)F;
    float vs = 0.f;
#pragma unroll
    for (int t = 0; t < V; t++) {
        float dx = acc[t].x - mean, dy = acc[t].y - mean,
              dz = acc[t].z - mean, dw = acc[t].w - mean;
        vs = fmaf(dx, dx, vs); vs = fmaf(dy, dy, vs);
        vs = fmaf(dz, dz, vs); vs = fmaf(dw, dw, vs);
    }
#pragma unroll
    for (int o = 16; o; o >>= 1) vs += __shfl_xor_sync(0xffffffffu, vs, o);
    float r = rsqrtf(vs / (float)F + 1e-5f);
    const float4* gp = (const float4*)lng;
    const float4* bp = (const float4*)lnb;
    float4* op = (float4*)(outp + (size_t)node * F);
#pragma unroll
    for (int t = 0; t < V; t++) {
        int f4 = lane + 32 * t;
        float4 g = gp[f4], bb = bp[f4], o4;
        float tx = (acc[t].x - mean) * r * g.x + bb.x;
        float ty = (acc[t].y - mean) * r * g.y + bb.y;
        float tz = (acc[t].z - mean) * r * g.z + bb.z;
        float tw = (acc[t].w - mean) * r * g.w + bb.w;
        o4.x = tx > 0.f ? tx : expm1f(tx);
        o4.y = ty > 0.f ? ty : expm1f(ty);
        o4.z = tz > 0.f ? tz : expm1f(tz);
        o4.w = tw > 0.f ? tw : expm1f(tw);
        op[f4] = o4;
    }
}

// ---------------- layer 3: fused projection, warp per node ----------------
__global__ void k_gemm3f(const float* __restrict__ X,
                         const float* __restrict__ Wq, const float* __restrict__ bq,
                         const float* __restrict__ Wk, const float* __restrict__ bk,
                         const float* __restrict__ Wv, const float* __restrict__ bv,
                         const float* __restrict__ Ws, const float* __restrict__ bs,
                         float* __restrict__ q, float* __restrict__ k,
                         float* __restrict__ v, float* __restrict__ sOut, int n) {
    int node = (blockIdx.x * blockDim.x + threadIdx.x) >> 5;
    int lane = threadIdx.x & 31;
    if (node >= n) return;
    const float* x = X + (size_t)node * 256;
    float a[8];
#pragma unroll
    for (int i = 0; i < 8; i++) a[i] = 0.f;
#pragma unroll
    for (int t = 0; t < 8; t++) {
        int i = lane + 32 * t;
        float xv = x[i];
        a[0] = fmaf(xv, Wq[i * 2], a[0]);
        a[1] = fmaf(xv, Wq[i * 2 + 1], a[1]);
        a[2] = fmaf(xv, Wk[i * 2], a[2]);
        a[3] = fmaf(xv, Wk[i * 2 + 1], a[3]);
        a[4] = fmaf(xv, Wv[i * 2], a[4]);
        a[5] = fmaf(xv, Wv[i * 2 + 1], a[5]);
        a[6] = fmaf(xv, Ws[i * 2], a[6]);
        a[7] = fmaf(xv, Ws[i * 2 + 1], a[7]);
    }
#pragma unroll
    for (int i = 0; i < 8; i++) {
#pragma unroll
        for (int o = 16; o; o >>= 1) a[i] += __shfl_xor_sync(0xffffffffu, a[i], o);
    }
    if (lane == 0) {
        q[(size_t)node * 2 + 0] = a[0] + bq[0];
        q[(size_t)node * 2 + 1] = a[1] + bq[1];
        k[(size_t)node * 2 + 0] = a[2] + bk[0];
        k[(size_t)node * 2 + 1] = a[3] + bk[1];
        v[(size_t)node * 2 + 0] = a[4] + bv[0];
        v[(size_t)node * 2 + 1] = a[5] + bv[1];
        sOut[(size_t)node * 2 + 0] = a[6] + bs[0];
        sOut[(size_t)node * 2 + 1] = a[7] + bs[1];
    }
}

// ---------------- layer-3 score: thread-per-edge ----------------
__global__ void k_alpha3(const int* __restrict__ src, const int* __restrict__ dst,
                         const float* __restrict__ q, const float* __restrict__ k,
                         int E, float scale) {
    int e = blockIdx.x * blockDim.x + threadIdx.x;
    if (e >= E) return;
    const float* qp = q + (size_t)dst[e] * 2;
    const float* kp = k + (size_t)src[e] * 2;
    g_alpha[e] = (qp[0] * kp[0] + qp[1] * kp[1]) * scale;
}

// ---------------- layer 3 CSR finalize ----------------
__global__ void k_final3(const int* __restrict__ src,
                         const float* __restrict__ v2, const float* __restrict__ s3,
                         float* __restrict__ out, int n) {
    int i = blockIdx.x * blockDim.x + threadIdx.x;
    if (i >= n) return;
    int s0 = g_rowptr[i], s1 = g_rowptr[i + 1];
    float m = -INFINITY;
    for (int j = s0; j < s1; j++) m = fmaxf(m, g_alpha[g_perm[j]]);
    float a0 = 0.f, a1 = 0.f;
    if (s1 > s0) {
        float dnm = 0.f;
        for (int j = s0; j < s1; j++) dnm += __expf(g_alpha[g_perm[j]] - m);
        float inv = 1.f / (dnm + 1e-16f);
        for (int j = s0; j < s1; j++) {
            int e = g_perm[j];
            float w = __expf(g_alpha[e] - m) * inv;
            const float* vr = v2 + (size_t)src[e] * 2;
            a0 = fmaf(w, vr[0], a0);
            a1 = fmaf(w, vr[1], a1);
        }
    }
    float h0 = a0 + s3[(size_t)i * 2 + 0];
    float h1 = a1 + s3[(size_t)i * 2 + 1];
    float mx = fmaxf(h0, h1);
    float lse = mx + logf(expf(h0 - mx) + expf(h1 - mx));
    out[2 * i + 0] = h0 - lse;
    out[2 * i + 1] = h1 - lse;
}

// ---------------- launch ----------------
static inline int cdiv(int a, int b) { return (a + b - 1) / b; }

extern "C" void kernel_launch(void* const* d_in, const int* in_sizes, int n_in,
                              void* d_out, int out_size) {
    const float* x = (const float*)d_in[0];
    const int* ei = (const int*)d_in[1];
    const int N = in_sizes[0] / 128;
    const int E = in_sizes[1] / 2;
    const int* src = ei;
    const int* dst = ei + E;

    const float *Wq1 = (const float*)d_in[2],  *bq1 = (const float*)d_in[3];
    const float *Wk1 = (const float*)d_in[4],  *bk1 = (const float*)d_in[5];
    const float *Wv1 = (const float*)d_in[6],  *bv1 = (const float*)d_in[7];
    const float *Ws1 = (const float*)d_in[8],  *bs1 = (const float*)d_in[9];
    const float *Wq2 = (const float*)d_in[10], *bq2 = (const float*)d_in[11];
    const float *Wk2 = (const float*)d_in[12], *bk2 = (const float*)d_in[13];
    const float *Wv2 = (const float*)d_in[14], *bv2 = (const float*)d_in[15];
    const float *Ws2 = (const float*)d_in[16], *bs2 = (const float*)d_in[17];
    const float *Wq3 = (const float*)d_in[18], *bq3 = (const float*)d_in[19];
    const float *Wk3 = (const float*)d_in[20], *bk3 = (const float*)d_in[21];
    const float *Wv3 = (const float*)d_in[22], *bv3 = (const float*)d_in[23];
    const float *Ws3 = (const float*)d_in[24], *bs3 = (const float*)d_in[25];
    const float *ln1g = (const float*)d_in[26], *ln1b = (const float*)d_in[27];
    const float *ln2g = (const float*)d_in[28], *ln2b = (const float*)d_in[29];
    float* out = (float*)d_out;

    static float *yb = nullptr, *hb = nullptr;
    static bool cfg = false;
    static cudaStream_t s2;
    static cudaEvent_t evFork, evJoin;
    if (!cfg) {
        void* p;
        cudaGetSymbolAddress(&p, g_y); yb = (float*)p;
        cudaGetSymbolAddress(&p, g_h); hb = (float*)p;
        cudaFuncSetAttribute(k_mma4, cudaFuncAttributeMaxDynamicSharedMemorySize, MMA_SMEM);
        cudaStreamCreateWithFlags(&s2, cudaStreamNonBlocking);
        cudaEventCreateWithFlags(&evFork, cudaEventDisableTiming);
        cudaEventCreateWithFlags(&evJoin, cudaEventDisableTiming);
        cfg = true;
    }

    float* q = yb;
    float* k = yb + (size_t)NN * 512;
    float* v = yb + (size_t)NN * 1024;
    float* sOut = yb + (size_t)NN * 1536;

    const int TB = 256;

    // ---- fork: CSR build on s2, overlapped with layer-1 GEMM ----
    cudaEventRecord(evFork, 0);
    cudaStreamWaitEvent(s2, evFork, 0);

    int n1 = N + 1;
    int nch = cdiv(n1, 256);
    k_zero_rowptr<<<cdiv(n1, TB), TB, 0, s2>>>(n1);
    k_count<<<cdiv(E, TB), TB, 0, s2>>>(dst, E);
    k_block_sums<<<nch, 256, 0, s2>>>(n1);
    k_scan_chunks<<<1, 32, 0, s2>>>(nch);
    k_block_scan<<<nch, 256, 0, s2>>>(n1);
    k_cursor<<<cdiv(N, TB), TB, 0, s2>>>(N);
    k_scatter<<<cdiv(E, TB), TB, 0, s2>>>(dst, E);
    cudaEventRecord(evJoin, s2);

    // ================= layer 1: K=128, F=512, H=4, C=128 =================
    {
        int K = 128, F = 512;
        dim3 grid(4 * F / 128, cdiv(N, 128));
        k_mma4<<<grid, 256, MMA_SMEM>>>(x, Wq1, bq1, q, Wk1, bk1, k, Wv1, bv1, v, Ws1, bs1, sOut, N, K, F);
        cudaStreamWaitEvent(0, evJoin, 0);
        k_alphaC<4, 128><<<cdiv(N * 32, TB), TB>>>(src, q, k, N, 0.08838834764831845f);
        k_aggC<4, 128><<<cdiv(N * 32, TB), TB>>>(src, v, sOut, ln1g, ln1b, hb, N);
    }
    // ================= layer 2: K=512, F=256, H=4, C=64 =================
    {
        int K = 512, F = 256;
        dim3 grid(4 * F / 128, cdiv(N, 128));
        k_mma4<<<grid, 256, MMA_SMEM>>>(hb, Wq2, bq2, q, Wk2, bk2, k, Wv2, bv2, v, Ws2, bs2, sOut, N, K, F);
        k_alphaC<4, 64><<<cdiv(N * 32, TB), TB>>>(src, q, k, N, 0.125f);
        k_aggC<4, 64><<<cdiv(N * 32, TB), TB>>>(src, v, sOut, ln2g, ln2b, hb, N);
    }
    // ================= layer 3: K=256, F=2, H=1, C=2 =================
    {
        k_gemm3f<<<cdiv(N * 32, TB), TB>>>(hb, Wq3, bq3, Wk3, bk3, Wv3, bv3, Ws3, bs3,
                                           q, k, v, sOut, N);
        k_alpha3<<<cdiv(E, TB), TB>>>(src, dst, q, k, E, 0.7071067811865475f);
        k_final3<<<cdiv(N, TB), TB>>>(src, v, sOut, out, N);
    }
}

// round 13
// speedup vs baseline: 1.1034x; 1.0393x over previous
#include <cuda_runtime.h>
#include <cstdint>
#include <stdint.h>
#include <math.h>

#define NN 50000
#define EE 400000

// ---------------- scratch (device globals) ----------------
__device__ float g_y[(size_t)NN * 2048];     // q|k|v|s slices, each NN*512
__device__ float g_h[(size_t)NN * 512];
__device__ int   g_rowptr[NN + 1];
__device__ int   g_cursor[NN];
__device__ int   g_perm[EE];
__device__ int   g_chunksum[256];

// ---------------- tf32 helpers ----------------
__device__ __forceinline__ uint32_t f2tf(float x) {
    uint32_t r;
    asm("cvt.rna.tf32.f32 %0, %1;" : "=r"(r) : "f"(x));
    return r;
}
__device__ __forceinline__ void mma_tf32(float* c, const uint32_t* a, const uint32_t* b) {
    asm volatile(
        "mma.sync.aligned.m16n8k8.row.col.f32.tf32.tf32.f32 "
        "{%0,%1,%2,%3}, {%4,%5,%6,%7}, {%8,%9}, {%0,%1,%2,%3};"
        : "+f"(c[0]), "+f"(c[1]), "+f"(c[2]), "+f"(c[3])
        : "r"(a[0]), "r"(a[1]), "r"(a[2]), "r"(a[3]), "r"(b[0]), "r"(b[1]));
}

// ---------------- CSR build (by dst) ----------------
__global__ void k_zero_rowptr(int n) {
    int i = blockIdx.x * blockDim.x + threadIdx.x;
    if (i < n) g_rowptr[i] = 0;
}
__global__ void k_count(const int* __restrict__ dst, int E) {
    int e = blockIdx.x * blockDim.x + threadIdx.x;
    if (e < E) atomicAdd(&g_rowptr[dst[e] + 1], 1);
}
__global__ void k_block_sums(int n) {
    __shared__ int sh[256];
    int i = blockIdx.x * 256 + threadIdx.x;
    sh[threadIdx.x] = (i < n) ? g_rowptr[i] : 0;
    __syncthreads();
    for (int o = 128; o > 0; o >>= 1) {
        if (threadIdx.x < o) sh[threadIdx.x] += sh[threadIdx.x + o];
        __syncthreads();
    }
    if (threadIdx.x == 0) g_chunksum[blockIdx.x] = sh[0];
}
__global__ void k_scan_chunks(int nch) {
    if (threadIdx.x == 0 && blockIdx.x == 0) {
        int running = 0;
        for (int i = 0; i < nch; i++) {
            int t = g_chunksum[i];
            g_chunksum[i] = running;
            running += t;
        }
    }
}
__global__ void k_block_scan(int n) {
    __shared__ int sh[256];
    int i = blockIdx.x * 256 + threadIdx.x;
    int t = threadIdx.x;
    sh[t] = (i < n) ? g_rowptr[i] : 0;
    __syncthreads();
    for (int o = 1; o < 256; o <<= 1) {
        int v = sh[t];
        int u = (t >= o) ? sh[t - o] : 0;
        __syncthreads();
        sh[t] = v + u;
        __syncthreads();
    }
    if (i < n) g_rowptr[i] = sh[t] + g_chunksum[blockIdx.x];
}
__global__ void k_cursor(int n) {
    int i = blockIdx.x * blockDim.x + threadIdx.x;
    if (i < n) g_cursor[i] = g_rowptr[i];
}
__global__ void k_scatter(const int* __restrict__ dst, int E) {
    int e = blockIdx.x * blockDim.x + threadIdx.x;
    if (e < E) {
        int p = atomicAdd(&g_cursor[dst[e]], 1);
        g_perm[p] = e;
    }
}

// ---------------- TF32x3 tensor-core GEMM (Round-10 best version) ----------------
#define AST 36
#define BST 136
#define MMA_SMEM ((2 * 128 * AST + 2 * 32 * BST) * 4)   // 71680 B

__global__ void __launch_bounds__(256) k_mma4(const float* __restrict__ Ag,
                                              const float* __restrict__ W0, const float* __restrict__ b0, float* __restrict__ o0,
                                              const float* __restrict__ W1, const float* __restrict__ b1, float* __restrict__ o1,
                                              const float* __restrict__ W2, const float* __restrict__ b2, float* __restrict__ o2,
                                              const float* __restrict__ W3, const float* __restrict__ b3, float* __restrict__ o3,
                                              int M, int K, int F) {
    extern __shared__ float sm[];
    float* As_hi = sm;
    float* As_lo = As_hi + 128 * AST;
    float* Bs_hi = As_lo + 128 * AST;
    float* Bs_lo = Bs_hi + 32 * BST;

    int tid = threadIdx.x;
    int warp = tid >> 5, lane = tid & 31;
    int wm = warp >> 2;
    int wn = warp & 3;
    int gid = lane >> 2;
    int l4 = lane & 3;

    int nb = F / 128;
    int bsel = blockIdx.x / nb;
    int bn = blockIdx.x % nb;
    int bm = blockIdx.y;
    const float* W = bsel == 0 ? W0 : bsel == 1 ? W1 : bsel == 2 ? W2 : W3;
    const float* bias = bsel == 0 ? b0 : bsel == 1 ? b1 : bsel == 2 ? b2 : b3;
    float* outp = bsel == 0 ? o0 : bsel == 1 ? o1 : bsel == 2 ? o2 : o3;

    float acc[4][4][4];
#pragma unroll
    for (int i = 0; i < 4; i++)
#pragma unroll
        for (int j = 0; j < 4; j++)
#pragma unroll
            for (int r = 0; r < 4; r++) acc[i][j][r] = 0.f;

    for (int k0 = 0; k0 < K; k0 += 32) {
        __syncthreads();
#pragma unroll
        for (int i = 0; i < 4; i++) {
            int r = (tid >> 3) + i * 32;
            int fc = (tid & 7) * 4;
            int gr = bm * 128 + r;
            float4 v = make_float4(0.f, 0.f, 0.f, 0.f);
            if (gr < M) v = *(const float4*)(Ag + (size_t)gr * K + k0 + fc);
            float4 h, l;
            h.x = __uint_as_float(f2tf(v.x)); l.x = __uint_as_float(f2tf(v.x - h.x));
            h.y = __uint_as_float(f2tf(v.y)); l.y = __uint_as_float(f2tf(v.y - h.y));
            h.z = __uint_as_float(f2tf(v.z)); l.z = __uint_as_float(f2tf(v.z - h.z));
            h.w = __uint_as_float(f2tf(v.w)); l.w = __uint_as_float(f2tf(v.w - h.w));
            *(float4*)(As_hi + r * AST + fc) = h;
            *(float4*)(As_lo + r * AST + fc) = l;
        }
        {
            int kk = tid >> 3;
            const float* Wrow = W + (size_t)(k0 + kk) * F + bn * 128;
#pragma unroll
            for (int i = 0; i < 4; i++) {
                int n = (tid & 7) * 4 + i * 32;
                float4 v = *(const float4*)(Wrow + n);
                float4 h, l;
                h.x = __uint_as_float(f2tf(v.x)); l.x = __uint_as_float(f2tf(v.x - h.x));
                h.y = __uint_as_float(f2tf(v.y)); l.y = __uint_as_float(f2tf(v.y - h.y));
                h.z = __uint_as_float(f2tf(v.z)); l.z = __uint_as_float(f2tf(v.z - h.z));
                h.w = __uint_as_float(f2tf(v.w)); l.w = __uint_as_float(f2tf(v.w - h.w));
                *(float4*)(Bs_hi + kk * BST + n) = h;
                *(float4*)(Bs_lo + kk * BST + n) = l;
            }
        }
        __syncthreads();

#pragma unroll
        for (int ks = 0; ks < 32; ks += 8) {
            uint32_t ah[4][4], al[4][4], bh[4][2], bl[4][2];
#pragma unroll
            for (int tm = 0; tm < 4; tm++) {
                int m0 = wm * 64 + tm * 16 + gid;
                const float* ph = As_hi + m0 * AST + ks + l4;
                const float* pl = As_lo + m0 * AST + ks + l4;
                ah[tm][0] = __float_as_uint(ph[0]);
                ah[tm][1] = __float_as_uint(ph[8 * AST]);
                ah[tm][2] = __float_as_uint(ph[4]);
                ah[tm][3] = __float_as_uint(ph[8 * AST + 4]);
                al[tm][0] = __float_as_uint(pl[0]);
                al[tm][1] = __float_as_uint(pl[8 * AST]);
                al[tm][2] = __float_as_uint(pl[4]);
                al[tm][3] = __float_as_uint(pl[8 * AST + 4]);
            }
#pragma unroll
            for (int tn = 0; tn < 4; tn++) {
                int n0 = wn * 32 + tn * 8 + gid;
                const float* ph = Bs_hi + (ks + l4) * BST + n0;
                const float* pl = Bs_lo + (ks + l4) * BST + n0;
                bh[tn][0] = __float_as_uint(ph[0]);
                bh[tn][1] = __float_as_uint(ph[4 * BST]);
                bl[tn][0] = __float_as_uint(pl[0]);
                bl[tn][1] = __float_as_uint(pl[4 * BST]);
            }
#pragma unroll
            for (int tm = 0; tm < 4; tm++)
#pragma unroll
                for (int tn = 0; tn < 4; tn++) {
                    mma_tf32(acc[tm][tn], ah[tm], bh[tn]);
                    mma_tf32(acc[tm][tn], ah[tm], bl[tn]);
                    mma_tf32(acc[tm][tn], al[tm], bh[tn]);
                }
        }
    }

#pragma unroll
    for (int tm = 0; tm < 4; tm++) {
        int r0 = bm * 128 + wm * 64 + tm * 16 + gid;
        int r1 = r0 + 8;
#pragma unroll
        for (int tn = 0; tn < 4; tn++) {
            int c = bn * 128 + wn * 32 + tn * 8 + l4 * 2;
            if (r0 < M) {
                outp[(size_t)r0 * F + c] = acc[tm][tn][0] + bias[c];
                outp[(size_t)r0 * F + c + 1] = acc[tm][tn][1] + bias[c + 1];
            }
            if (r1 < M) {
                outp[(size_t)r1 * F + c] = acc[tm][tn][2] + bias[c];
                outp[(size_t)r1 * F + c + 1] = acc[tm][tn][3] + bias[c + 1];
            }
        }
    }
}

// ---------------- FUSED edge phase: online softmax + aggregate + skip + LN + ELU ----------
// warp per node; q cached in registers; single pass over CSR segment gathering k & v.
template <int H, int C>
__global__ void k_edge(const int* __restrict__ src,
                       const float* __restrict__ q, const float* __restrict__ k,
                       const float* __restrict__ v, const float* __restrict__ sskip,
                       const float* __restrict__ lng, const float* __restrict__ lnb,
                       float* __restrict__ outp, int n, float scale) {
    constexpr int F = H * C, T = F / 128;
    int node = (blockIdx.x * blockDim.x + threadIdx.x) >> 5;
    int lane = threadIdx.x & 31;
    if (node >= n) return;
    int s0 = g_rowptr[node], s1 = g_rowptr[node + 1];

    float4 qr[T];
    const float4* qp = (const float4*)(q + (size_t)node * F);
#pragma unroll
    for (int t = 0; t < T; t++) qr[t] = qp[lane + 32 * t];

    float m[H], den[H];
#pragma unroll
    for (int h = 0; h < H; h++) { m[h] = -INFINITY; den[h] = 0.f; }
    float4 acc[T];
#pragma unroll
    for (int t = 0; t < T; t++) acc[t] = make_float4(0.f, 0.f, 0.f, 0.f);

    for (int j = s0; j < s1; j++) {
        int e = g_perm[j];
        int sv = src[e];
        const float4* kp = (const float4*)(k + (size_t)sv * F);
        const float4* vp = (const float4*)(v + (size_t)sv * F);

        // per-head dot
        float d[H];
#pragma unroll
        for (int h = 0; h < H; h++) d[h] = 0.f;
        float4 vreg[T];
#pragma unroll
        for (int t = 0; t < T; t++) {
            float4 a = qr[t], b = kp[lane + 32 * t];
            vreg[t] = vp[lane + 32 * t];   // issue v load early, overlap with reduction
            float dd = a.x * b.x + a.y * b.y + a.z * b.z + a.w * b.w;
            if constexpr (C == 128) {
                d[t] += dd;
            } else {
                if (lane < 16) d[2 * t] += dd;
                else d[2 * t + 1] += dd;
            }
        }
#pragma unroll
        for (int h = 0; h < H; h++) {
#pragma unroll
            for (int o = 16; o; o >>= 1) d[h] += __shfl_xor_sync(0xffffffffu, d[h], o);
            d[h] *= scale;
        }

        // online softmax update
        float fa[H], w[H];
#pragma unroll
        for (int h = 0; h < H; h++) {
            float nm = fmaxf(m[h], d[h]);
            fa[h] = __expf(m[h] - nm);     // exp(-inf)=0 on first edge
            w[h] = __expf(d[h] - nm);
            den[h] = den[h] * fa[h] + w[h];
            m[h] = nm;
        }
#pragma unroll
        for (int t = 0; t < T; t++) {
            float f, ww;
            if constexpr (C == 128) { f = fa[t]; ww = w[t]; }
            else {
                int h = 2 * t + (lane < 16 ? 0 : 1);
                f = fa[h]; ww = w[h];
            }
            acc[t].x = fmaf(ww, vreg[t].x, acc[t].x * f);
            acc[t].y = fmaf(ww, vreg[t].y, acc[t].y * f);
            acc[t].z = fmaf(ww, vreg[t].z, acc[t].z * f);
            acc[t].w = fmaf(ww, vreg[t].w, acc[t].w * f);
        }
    }

    // normalize
    float inv[H];
#pragma unroll
    for (int h = 0; h < H; h++) inv[h] = 1.f / (den[h] + 1e-16f);
#pragma unroll
    for (int t = 0; t < T; t++) {
        float f;
        if constexpr (C == 128) f = inv[t];
        else f = (lane < 16) ? inv[2 * t] : inv[2 * t + 1];
        acc[t].x *= f; acc[t].y *= f; acc[t].z *= f; acc[t].w *= f;
    }

    // skip
    const float4* sr = (const float4*)(sskip + (size_t)node * F);
#pragma unroll
    for (int t = 0; t < T; t++) {
        float4 b = sr[lane + 32 * t];
        acc[t].x += b.x; acc[t].y += b.y; acc[t].z += b.z; acc[t].w += b.w;
    }

    // LayerNorm + ELU
    float s = 0.f;
#pragma unroll
    for (int t = 0; t < T; t++) s += acc[t].x + acc[t].y + acc[t].z + acc[t].w;
#pragma unroll
    for (int o = 16; o; o >>= 1) s += __shfl_xor_sync(0xffffffffu, s, o);
    float mean = s / (float)F;
    float vs = 0.f;
#pragma unroll
    for (int t = 0; t < T; t++) {
        float dx = acc[t].x - mean, dy = acc[t].y - mean,
              dz = acc[t].z - mean, dw = acc[t].w - mean;
        vs = fmaf(dx, dx, vs); vs = fmaf(dy, dy, vs);
        vs = fmaf(dz, dz, vs); vs = fmaf(dw, dw, vs);
    }
#pragma unroll
    for (int o = 16; o; o >>= 1) vs += __shfl_xor_sync(0xffffffffu, vs, o);
    float r = rsqrtf(vs / (float)F + 1e-5f);
    const float4* gp = (const float4*)lng;
    const float4* bp = (const float4*)lnb;
    float4* op = (float4*)(outp + (size_t)node * F);
#pragma unroll
    for (int t = 0; t < T; t++) {
        int f4 = lane + 32 * t;
        float4 g = gp[f4], bb = bp[f4], o4;
        float tx = (acc[t].x - mean) * r * g.x + bb.x;
        float ty = (acc[t].y - mean) * r * g.y + bb.y;
        float tz = (acc[t].z - mean) * r * g.z + bb.z;
        float tw = (acc[t].w - mean) * r * g.w + bb.w;
        o4.x = tx > 0.f ? tx : expm1f(tx);
        o4.y = ty > 0.f ? ty : expm1f(ty);
        o4.z = tz > 0.f ? tz : expm1f(tz);
        o4.w = tw > 0.f ? tw : expm1f(tw);
        op[f4] = o4;
    }
}

// ---------------- layer 3: fused projection, warp per node ----------------
__global__ void k_gemm3f(const float* __restrict__ X,
                         const float* __restrict__ Wq, const float* __restrict__ bq,
                         const float* __restrict__ Wk, const float* __restrict__ bk,
                         const float* __restrict__ Wv, const float* __restrict__ bv,
                         const float* __restrict__ Ws, const float* __restrict__ bs,
                         float* __restrict__ q, float* __restrict__ k,
                         float* __restrict__ v, float* __restrict__ sOut, int n) {
    int node = (blockIdx.x * blockDim.x + threadIdx.x) >> 5;
    int lane = threadIdx.x & 31;
    if (node >= n) return;
    const float* x = X + (size_t)node * 256;
    float a[8];
#pragma unroll
    for (int i = 0; i < 8; i++) a[i] = 0.f;
#pragma unroll
    for (int t = 0; t < 8; t++) {
        int i = lane + 32 * t;
        float xv = x[i];
        a[0] = fmaf(xv, Wq[i * 2], a[0]);
        a[1] = fmaf(xv, Wq[i * 2 + 1], a[1]);
        a[2] = fmaf(xv, Wk[i * 2], a[2]);
        a[3] = fmaf(xv, Wk[i * 2 + 1], a[3]);
        a[4] = fmaf(xv, Wv[i * 2], a[4]);
        a[5] = fmaf(xv, Wv[i * 2 + 1], a[5]);
        a[6] = fmaf(xv, Ws[i * 2], a[6]);
        a[7] = fmaf(xv, Ws[i * 2 + 1], a[7]);
    }
#pragma unroll
    for (int i = 0; i < 8; i++) {
#pragma unroll
        for (int o = 16; o; o >>= 1) a[i] += __shfl_xor_sync(0xffffffffu, a[i], o);
    }
    if (lane == 0) {
        q[(size_t)node * 2 + 0] = a[0] + bq[0];
        q[(size_t)node * 2 + 1] = a[1] + bq[1];
        k[(size_t)node * 2 + 0] = a[2] + bk[0];
        k[(size_t)node * 2 + 1] = a[3] + bk[1];
        v[(size_t)node * 2 + 0] = a[4] + bv[0];
        v[(size_t)node * 2 + 1] = a[5] + bv[1];
        sOut[(size_t)node * 2 + 0] = a[6] + bs[0];
        sOut[(size_t)node * 2 + 1] = a[7] + bs[1];
    }
}

// ---------------- layer 3 fused finalize: online softmax + skip + log_softmax -----------
__global__ void k_final3(const int* __restrict__ src,
                         const float* __restrict__ q2, const float* __restrict__ k2,
                         const float* __restrict__ v2, const float* __restrict__ s3,
                         float* __restrict__ out, int n, float scale) {
    int i = blockIdx.x * blockDim.x + threadIdx.x;
    if (i >= n) return;
    int s0 = g_rowptr[i], s1 = g_rowptr[i + 1];
    float q0 = q2[(size_t)i * 2 + 0], q1 = q2[(size_t)i * 2 + 1];
    float m = -INFINITY, den = 0.f, a0 = 0.f, a1 = 0.f;
    for (int j = s0; j < s1; j++) {
        int e = g_perm[j];
        int sv = src[e];
        float sc = (q0 * k2[(size_t)sv * 2] + q1 * k2[(size_t)sv * 2 + 1]) * scale;
        float nm = fmaxf(m, sc);
        float fa = __expf(m - nm);
        float w = __expf(sc - nm);
        den = den * fa + w;
        a0 = fmaf(w, v2[(size_t)sv * 2 + 0], a0 * fa);
        a1 = fmaf(w, v2[(size_t)sv * 2 + 1], a1 * fa);
        m = nm;
    }
    float inv = 1.f / (den + 1e-16f);
    a0 *= inv; a1 *= inv;
    float h0 = a0 + s3[(size_t)i * 2 + 0];
    float h1 = a1 + s3[(size_t)i * 2 + 1];
    float mx = fmaxf(h0, h1);
    float lse = mx + logf(expf(h0 - mx) + expf(h1 - mx));
    out[2 * i + 0] = h0 - lse;
    out[2 * i + 1] = h1 - lse;
}

// ---------------- launch ----------------
static inline int cdiv(int a, int b) { return (a + b - 1) / b; }

extern "C" void kernel_launch(void* const* d_in, const int* in_sizes, int n_in,
                              void* d_out, int out_size) {
    const float* x = (const float*)d_in[0];
    const int* ei = (const int*)d_in[1];
    const int N = in_sizes[0] / 128;
    const int E = in_sizes[1] / 2;
    const int* src = ei;
    const int* dst = ei + E;

    const float *Wq1 = (const float*)d_in[2],  *bq1 = (const float*)d_in[3];
    const float *Wk1 = (const float*)d_in[4],  *bk1 = (const float*)d_in[5];
    const float *Wv1 = (const float*)d_in[6],  *bv1 = (const float*)d_in[7];
    const float *Ws1 = (const float*)d_in[8],  *bs1 = (const float*)d_in[9];
    const float *Wq2 = (const float*)d_in[10], *bq2 = (const float*)d_in[11];
    const float *Wk2 = (const float*)d_in[12], *bk2 = (const float*)d_in[13];
    const float *Wv2 = (const float*)d_in[14], *bv2 = (const float*)d_in[15];
    const float *Ws2 = (const float*)d_in[16], *bs2 = (const float*)d_in[17];
    const float *Wq3 = (const float*)d_in[18], *bq3 = (const float*)d_in[19];
    const float *Wk3 = (const float*)d_in[20], *bk3 = (const float*)d_in[21];
    const float *Wv3 = (const float*)d_in[22], *bv3 = (const float*)d_in[23];
    const float *Ws3 = (const float*)d_in[24], *bs3 = (const float*)d_in[25];
    const float *ln1g = (const float*)d_in[26], *ln1b = (const float*)d_in[27];
    const float *ln2g = (const float*)d_in[28], *ln2b = (const float*)d_in[29];
    float* out = (float*)d_out;

    static float *yb = nullptr, *hb = nullptr;
    static bool cfg = false;
    static cudaStream_t s2;
    static cudaEvent_t evFork, evJoin;
    if (!cfg) {
        void* p;
        cudaGetSymbolAddress(&p, g_y); yb = (float*)p;
        cudaGetSymbolAddress(&p, g_h); hb = (float*)p;
        cudaFuncSetAttribute(k_mma4, cudaFuncAttributeMaxDynamicSharedMemorySize, MMA_SMEM);
        cudaStreamCreateWithFlags(&s2, cudaStreamNonBlocking);
        cudaEventCreateWithFlags(&evFork, cudaEventDisableTiming);
        cudaEventCreateWithFlags(&evJoin, cudaEventDisableTiming);
        cfg = true;
    }

    float* q = yb;
    float* k = yb + (size_t)NN * 512;
    float* v = yb + (size_t)NN * 1024;
    float* sOut = yb + (size_t)NN * 1536;

    const int TB = 256;

    // ---- fork: CSR build on s2, overlapped with layer-1 GEMM ----
    cudaEventRecord(evFork, 0);
    cudaStreamWaitEvent(s2, evFork, 0);

    int n1 = N + 1;
    int nch = cdiv(n1, 256);
    k_zero_rowptr<<<cdiv(n1, TB), TB, 0, s2>>>(n1);
    k_count<<<cdiv(E, TB), TB, 0, s2>>>(dst, E);
    k_block_sums<<<nch, 256, 0, s2>>>(n1);
    k_scan_chunks<<<1, 32, 0, s2>>>(nch);
    k_block_scan<<<nch, 256, 0, s2>>>(n1);
    k_cursor<<<cdiv(N, TB), TB, 0, s2>>>(N);
    k_scatter<<<cdiv(E, TB), TB, 0, s2>>>(dst, E);
    cudaEventRecord(evJoin, s2);

    // ================= layer 1: K=128, F=512, H=4, C=128 =================
    {
        int K = 128, F = 512;
        dim3 grid(4 * F / 128, cdiv(N, 128));
        k_mma4<<<grid, 256, MMA_SMEM>>>(x, Wq1, bq1, q, Wk1, bk1, k, Wv1, bv1, v, Ws1, bs1, sOut, N, K, F);
        cudaStreamWaitEvent(0, evJoin, 0);
        k_edge<4, 128><<<cdiv(N * 32, TB), TB>>>(src, q, k, v, sOut, ln1g, ln1b, hb, N,
                                                 0.08838834764831845f);
    }
    // ================= layer 2: K=512, F=256, H=4, C=64 =================
    {
        int K = 512, F = 256;
        dim3 grid(4 * F / 128, cdiv(N, 128));
        k_mma4<<<grid, 256, MMA_SMEM>>>(hb, Wq2, bq2, q, Wk2, bk2, k, Wv2, bv2, v, Ws2, bs2, sOut, N, K, F);
        k_edge<4, 64><<<cdiv(N * 32, TB), TB>>>(src, q, k, v, sOut, ln2g, ln2b, hb, N, 0.125f);
    }
    // ================= layer 3: K=256, F=2, H=1, C=2 =================
    {
        k_gemm3f<<<cdiv(N * 32, TB), TB>>>(hb, Wq3, bq3, Wk3, bk3, Wv3, bv3, Ws3, bs3,
                                           q, k, v, sOut, N);
        k_final3<<<cdiv(N, TB), TB>>>(src, q, k, v, sOut, out, N, 0.7071067811865475f);
    }
}

// round 14
// speedup vs baseline: 1.4913x; 1.3515x over previous
#include <cuda_runtime.h>
#include <cuda_bf16.h>
#include <cstdint>
#include <stdint.h>
#include <math.h>

#define NN 50000
#define EE 400000

// ---------------- scratch (device globals) ----------------
__device__ float g_y[(size_t)NN * 2048];     // q|k|v|s slices, each NN*512
__device__ float g_h[(size_t)NN * 512];
__device__ int   g_rowptr[NN + 1];
__device__ int   g_cursor[NN];
__device__ int   g_perm[EE];
__device__ int   g_chunksum[256];

// ---------------- helpers ----------------
__device__ __forceinline__ uint32_t s2u(const void* p) {
    return (uint32_t)__cvta_generic_to_shared(p);
}
__device__ __forceinline__ void mma_bf16(float* c, const uint32_t* a, const uint32_t* b) {
    asm volatile(
        "mma.sync.aligned.m16n8k16.row.col.f32.bf16.bf16.f32 "
        "{%0,%1,%2,%3}, {%4,%5,%6,%7}, {%8,%9}, {%0,%1,%2,%3};"
        : "+f"(c[0]), "+f"(c[1]), "+f"(c[2]), "+f"(c[3])
        : "r"(a[0]), "r"(a[1]), "r"(a[2]), "r"(a[3]), "r"(b[0]), "r"(b[1]));
}
__device__ __forceinline__ void ldsm4(uint32_t addr, uint32_t& r0, uint32_t& r1,
                                      uint32_t& r2, uint32_t& r3) {
    asm volatile("ldmatrix.sync.aligned.m8n8.x4.shared.b16 {%0,%1,%2,%3}, [%4];"
                 : "=r"(r0), "=r"(r1), "=r"(r2), "=r"(r3) : "r"(addr));
}
__device__ __forceinline__ void ldsm4t(uint32_t addr, uint32_t& r0, uint32_t& r1,
                                       uint32_t& r2, uint32_t& r3) {
    asm volatile("ldmatrix.sync.aligned.m8n8.x4.trans.shared.b16 {%0,%1,%2,%3}, [%4];"
                 : "=r"(r0), "=r"(r1), "=r"(r2), "=r"(r3) : "r"(addr));
}
// pack (lo, hi) floats into bf16x2 (low 16 bits = first arg) + residuals
__device__ __forceinline__ void split2(float x, float y, uint32_t& hi, uint32_t& lo) {
    __nv_bfloat16 hx = __float2bfloat16_rn(x);
    __nv_bfloat16 hy = __float2bfloat16_rn(y);
    __nv_bfloat162 hh; hh.x = hx; hh.y = hy;
    hi = *(uint32_t*)&hh;
    __nv_bfloat162 ll;
    ll.x = __float2bfloat16_rn(x - __bfloat162float(hx));
    ll.y = __float2bfloat16_rn(y - __bfloat162float(hy));
    lo = *(uint32_t*)&ll;
}

// ---------------- CSR build (by dst) ----------------
__global__ void k_zero_rowptr(int n) {
    int i = blockIdx.x * blockDim.x + threadIdx.x;
    if (i < n) g_rowptr[i] = 0;
}
__global__ void k_count(const int* __restrict__ dst, int E) {
    int e = blockIdx.x * blockDim.x + threadIdx.x;
    if (e < E) atomicAdd(&g_rowptr[dst[e] + 1], 1);
}
__global__ void k_block_sums(int n) {
    __shared__ int sh[256];
    int i = blockIdx.x * 256 + threadIdx.x;
    sh[threadIdx.x] = (i < n) ? g_rowptr[i] : 0;
    __syncthreads();
    for (int o = 128; o > 0; o >>= 1) {
        if (threadIdx.x < o) sh[threadIdx.x] += sh[threadIdx.x + o];
        __syncthreads();
    }
    if (threadIdx.x == 0) g_chunksum[blockIdx.x] = sh[0];
}
__global__ void k_scan_chunks(int nch) {
    if (threadIdx.x == 0 && blockIdx.x == 0) {
        int running = 0;
        for (int i = 0; i < nch; i++) {
            int t = g_chunksum[i];
            g_chunksum[i] = running;
            running += t;
        }
    }
}
__global__ void k_block_scan(int n) {
    __shared__ int sh[256];
    int i = blockIdx.x * 256 + threadIdx.x;
    int t = threadIdx.x;
    sh[t] = (i < n) ? g_rowptr[i] : 0;
    __syncthreads();
    for (int o = 1; o < 256; o <<= 1) {
        int v = sh[t];
        int u = (t >= o) ? sh[t - o] : 0;
        __syncthreads();
        sh[t] = v + u;
        __syncthreads();
    }
    if (i < n) g_rowptr[i] = sh[t] + g_chunksum[blockIdx.x];
}
__global__ void k_cursor(int n) {
    int i = blockIdx.x * blockDim.x + threadIdx.x;
    if (i < n) g_cursor[i] = g_rowptr[i];
}
__global__ void k_scatter(const int* __restrict__ dst, int E) {
    int e = blockIdx.x * blockDim.x + threadIdx.x;
    if (e < E) {
        int p = atomicAdd(&g_cursor[dst[e]], 1);
        g_perm[p] = e;
    }
}

// ---------------- BF16x3 tensor-core GEMM ----------------
// smem: A [128 m][40 bf16] (80B rows, conflict-free ldmatrix), hi+lo
//       B [32 k][136 bf16] (272B rows, conflict-free ldmatrix.trans), hi+lo
#define A_STR 40     // bf16 per A row (20 uint32, 80 B)
#define B_STR 136    // bf16 per B row (68 uint32, 272 B)

__global__ void __launch_bounds__(256) k_mma4(const float* __restrict__ Ag,
                                              const float* __restrict__ W0, const float* __restrict__ b0, float* __restrict__ o0,
                                              const float* __restrict__ W1, const float* __restrict__ b1, float* __restrict__ o1,
                                              const float* __restrict__ W2, const float* __restrict__ b2, float* __restrict__ o2,
                                              const float* __restrict__ W3, const float* __restrict__ b3, float* __restrict__ o3,
                                              int M, int K, int F) {
    __shared__ __align__(16) __nv_bfloat16 As_hi[128 * A_STR];
    __shared__ __align__(16) __nv_bfloat16 As_lo[128 * A_STR];
    __shared__ __align__(16) __nv_bfloat16 Bs_hi[32 * B_STR];
    __shared__ __align__(16) __nv_bfloat16 Bs_lo[32 * B_STR];

    int tid = threadIdx.x;
    int warp = tid >> 5, lane = tid & 31;
    int wm = warp >> 2;        // 0..1
    int wn = warp & 3;         // 0..3
    int gid = lane >> 2;
    int l4 = lane & 3;

    int nb = F / 128;
    int bsel = blockIdx.x / nb;
    int bn = blockIdx.x % nb;
    int bm = blockIdx.y;
    const float* W = bsel == 0 ? W0 : bsel == 1 ? W1 : bsel == 2 ? W2 : W3;
    const float* bias = bsel == 0 ? b0 : bsel == 1 ? b1 : bsel == 2 ? b2 : b3;
    float* outp = bsel == 0 ? o0 : bsel == 1 ? o1 : bsel == 2 ? o2 : o3;

    uint32_t* Ah32 = (uint32_t*)As_hi;
    uint32_t* Al32 = (uint32_t*)As_lo;
    uint32_t* Bh32 = (uint32_t*)Bs_hi;
    uint32_t* Bl32 = (uint32_t*)Bs_lo;
    uint32_t sAh = s2u(As_hi), sAl = s2u(As_lo);
    uint32_t sBh = s2u(Bs_hi), sBl = s2u(Bs_lo);

    // ldmatrix lane-pointer components
    int q = lane >> 3, r8 = lane & 7;
    // A: row = mbase + (q&1)*8 + r8 ; col = ks + (q>>1)*8
    int a_row_off = (q & 1) * 8 + r8;
    int a_col_off = (q >> 1) * 8;
    // B: k = ks + (q&1)*8 + r8 ; n-block select = q>>1
    int b_k_off = (q & 1) * 8 + r8;
    int b_nblk = q >> 1;

    float acc[4][4][4];
#pragma unroll
    for (int i = 0; i < 4; i++)
#pragma unroll
        for (int j = 0; j < 4; j++)
#pragma unroll
            for (int r = 0; r < 4; r++) acc[i][j][r] = 0.f;

    for (int k0 = 0; k0 < K; k0 += 32) {
        __syncthreads();
        // ---- fill A tile [128 m][32 k] as bf16 hi/lo ----
#pragma unroll
        for (int i = 0; i < 4; i++) {
            int r = (tid >> 3) + i * 32;
            int fc = (tid & 7) * 4;
            int gr = bm * 128 + r;
            float4 v = make_float4(0.f, 0.f, 0.f, 0.f);
            if (gr < M) v = *(const float4*)(Ag + (size_t)gr * K + k0 + fc);
            uint32_t h0, l0, h1, l1;
            split2(v.x, v.y, h0, l0);
            split2(v.z, v.w, h1, l1);
            int base = r * (A_STR / 2) + fc / 2;
            Ah32[base] = h0; Ah32[base + 1] = h1;
            Al32[base] = l0; Al32[base + 1] = l1;
        }
        // ---- fill B tile [32 k][128 n] as bf16 hi/lo ----
        {
            int kk = tid >> 3;
            const float* Wrow = W + (size_t)(k0 + kk) * F + bn * 128;
#pragma unroll
            for (int i = 0; i < 4; i++) {
                int n = (tid & 7) * 4 + i * 32;
                float4 v = *(const float4*)(Wrow + n);
                uint32_t h0, l0, h1, l1;
                split2(v.x, v.y, h0, l0);
                split2(v.z, v.w, h1, l1);
                int base = kk * (B_STR / 2) + n / 2;
                Bh32[base] = h0; Bh32[base + 1] = h1;
                Bl32[base] = l0; Bl32[base + 1] = l1;
            }
        }
        __syncthreads();

#pragma unroll
        for (int ks = 0; ks < 32; ks += 16) {
            uint32_t ah[4][4], al[4][4], bh[4][2], bl[4][2];
#pragma unroll
            for (int tm = 0; tm < 4; tm++) {
                int mbase = wm * 64 + tm * 16;
                uint32_t off = (uint32_t)((mbase + a_row_off) * (A_STR * 2) +
                                          (ks + a_col_off) * 2);
                ldsm4(sAh + off, ah[tm][0], ah[tm][1], ah[tm][2], ah[tm][3]);
                ldsm4(sAl + off, al[tm][0], al[tm][1], al[tm][2], al[tm][3]);
            }
#pragma unroll
            for (int tnp = 0; tnp < 2; tnp++) {
                int n0 = wn * 32 + (tnp * 2 + b_nblk) * 8;
                uint32_t off = (uint32_t)((ks + b_k_off) * (B_STR * 2) + n0 * 2);
                ldsm4t(sBh + off, bh[2 * tnp][0], bh[2 * tnp][1],
                       bh[2 * tnp + 1][0], bh[2 * tnp + 1][1]);
                ldsm4t(sBl + off, bl[2 * tnp][0], bl[2 * tnp][1],
                       bl[2 * tnp + 1][0], bl[2 * tnp + 1][1]);
            }
#pragma unroll
            for (int tm = 0; tm < 4; tm++)
#pragma unroll
                for (int tn = 0; tn < 4; tn++) {
                    mma_bf16(acc[tm][tn], ah[tm], bh[tn]);
                    mma_bf16(acc[tm][tn], ah[tm], bl[tn]);
                    mma_bf16(acc[tm][tn], al[tm], bh[tn]);
                }
        }
    }

    // ---- epilogue (same D layout as m16n8k8) ----
#pragma unroll
    for (int tm = 0; tm < 4; tm++) {
        int r0 = bm * 128 + wm * 64 + tm * 16 + gid;
        int r1 = r0 + 8;
#pragma unroll
        for (int tn = 0; tn < 4; tn++) {
            int c = bn * 128 + wn * 32 + tn * 8 + l4 * 2;
            if (r0 < M) {
                outp[(size_t)r0 * F + c] = acc[tm][tn][0] + bias[c];
                outp[(size_t)r0 * F + c + 1] = acc[tm][tn][1] + bias[c + 1];
            }
            if (r1 < M) {
                outp[(size_t)r1 * F + c] = acc[tm][tn][2] + bias[c];
                outp[(size_t)r1 * F + c + 1] = acc[tm][tn][3] + bias[c + 1];
            }
        }
    }
}

// ---------------- FUSED edge phase: online softmax + aggregate + skip + LN + ELU ----------
template <int H, int C>
__global__ void k_edge(const int* __restrict__ src,
                       const float* __restrict__ q, const float* __restrict__ k,
                       const float* __restrict__ v, const float* __restrict__ sskip,
                       const float* __restrict__ lng, const float* __restrict__ lnb,
                       float* __restrict__ outp, int n, float scale) {
    constexpr int F = H * C, T = F / 128;
    int node = (blockIdx.x * blockDim.x + threadIdx.x) >> 5;
    int lane = threadIdx.x & 31;
    if (node >= n) return;
    int s0 = g_rowptr[node], s1 = g_rowptr[node + 1];

    float4 qr[T];
    const float4* qp = (const float4*)(q + (size_t)node * F);
#pragma unroll
    for (int t = 0; t < T; t++) qr[t] = qp[lane + 32 * t];

    float m[H], den[H];
#pragma unroll
    for (int h = 0; h < H; h++) { m[h] = -INFINITY; den[h] = 0.f; }
    float4 acc[T];
#pragma unroll
    for (int t = 0; t < T; t++) acc[t] = make_float4(0.f, 0.f, 0.f, 0.f);

    for (int j = s0; j < s1; j++) {
        int e = g_perm[j];
        int sv = src[e];
        const float4* kp = (const float4*)(k + (size_t)sv * F);
        const float4* vp = (const float4*)(v + (size_t)sv * F);

        float d[H];
#pragma unroll
        for (int h = 0; h < H; h++) d[h] = 0.f;
        float4 vreg[T];
#pragma unroll
        for (int t = 0; t < T; t++) {
            float4 a = qr[t], b = kp[lane + 32 * t];
            vreg[t] = vp[lane + 32 * t];
            float dd = a.x * b.x + a.y * b.y + a.z * b.z + a.w * b.w;
            if constexpr (C == 128) {
                d[t] += dd;
            } else {
                if (lane < 16) d[2 * t] += dd;
                else d[2 * t + 1] += dd;
            }
        }
#pragma unroll
        for (int h = 0; h < H; h++) {
#pragma unroll
            for (int o = 16; o; o >>= 1) d[h] += __shfl_xor_sync(0xffffffffu, d[h], o);
            d[h] *= scale;
        }

        float fa[H], w[H];
#pragma unroll
        for (int h = 0; h < H; h++) {
            float nm = fmaxf(m[h], d[h]);
            fa[h] = __expf(m[h] - nm);
            w[h] = __expf(d[h] - nm);
            den[h] = den[h] * fa[h] + w[h];
            m[h] = nm;
        }
#pragma unroll
        for (int t = 0; t < T; t++) {
            float f, ww;
            if constexpr (C == 128) { f = fa[t]; ww = w[t]; }
            else {
                int h = 2 * t + (lane < 16 ? 0 : 1);
                f = fa[h]; ww = w[h];
            }
            acc[t].x = fmaf(ww, vreg[t].x, acc[t].x * f);
            acc[t].y = fmaf(ww, vreg[t].y, acc[t].y * f);
            acc[t].z = fmaf(ww, vreg[t].z, acc[t].z * f);
            acc[t].w = fmaf(ww, vreg[t].w, acc[t].w * f);
        }
    }

    float inv[H];
#pragma unroll
    for (int h = 0; h < H; h++) inv[h] = 1.f / (den[h] + 1e-16f);
#pragma unroll
    for (int t = 0; t < T; t++) {
        float f;
        if constexpr (C == 128) f = inv[t];
        else f = (lane < 16) ? inv[2 * t] : inv[2 * t + 1];
        acc[t].x *= f; acc[t].y *= f; acc[t].z *= f; acc[t].w *= f;
    }

    const float4* sr = (const float4*)(sskip + (size_t)node * F);
#pragma unroll
    for (int t = 0; t < T; t++) {
        float4 b = sr[lane + 32 * t];
        acc[t].x += b.x; acc[t].y += b.y; acc[t].z += b.z; acc[t].w += b.w;
    }

    float s = 0.f;
#pragma unroll
    for (int t = 0; t < T; t++) s += acc[t].x + acc[t].y + acc[t].z + acc[t].w;
#pragma unroll
    for (int o = 16; o; o >>= 1) s += __shfl_xor_sync(0xffffffffu, s, o);
    float mean = s / (float)F;
    float vs = 0.f;
#pragma unroll
    for (int t = 0; t < T; t++) {
        float dx = acc[t].x - mean, dy = acc[t].y - mean,
              dz = acc[t].z - mean, dw = acc[t].w - mean;
        vs = fmaf(dx, dx, vs); vs = fmaf(dy, dy, vs);
        vs = fmaf(dz, dz, vs); vs = fmaf(dw, dw, vs);
    }
#pragma unroll
    for (int o = 16; o; o >>= 1) vs += __shfl_xor_sync(0xffffffffu, vs, o);
    float r = rsqrtf(vs / (float)F + 1e-5f);
    const float4* gp = (const float4*)lng;
    const float4* bp = (const float4*)lnb;
    float4* op = (float4*)(outp + (size_t)node * F);
#pragma unroll
    for (int t = 0; t < T; t++) {
        int f4 = lane + 32 * t;
        float4 g = gp[f4], bb = bp[f4], o4;
        float tx = (acc[t].x - mean) * r * g.x + bb.x;
        float ty = (acc[t].y - mean) * r * g.y + bb.y;
        float tz = (acc[t].z - mean) * r * g.z + bb.z;
        float tw = (acc[t].w - mean) * r * g.w + bb.w;
        o4.x = tx > 0.f ? tx : expm1f(tx);
        o4.y = ty > 0.f ? ty : expm1f(ty);
        o4.z = tz > 0.f ? tz : expm1f(tz);
        o4.w = tw > 0.f ? tw : expm1f(tw);
        op[f4] = o4;
    }
}

// ---------------- layer 3: fused projection, warp per node ----------------
__global__ void k_gemm3f(const float* __restrict__ X,
                         const float* __restrict__ Wq, const float* __restrict__ bq,
                         const float* __restrict__ Wk, const float* __restrict__ bk,
                         const float* __restrict__ Wv, const float* __restrict__ bv,
                         const float* __restrict__ Ws, const float* __restrict__ bs,
                         float* __restrict__ q, float* __restrict__ k,
                         float* __restrict__ v, float* __restrict__ sOut, int n) {
    int node = (blockIdx.x * blockDim.x + threadIdx.x) >> 5;
    int lane = threadIdx.x & 31;
    if (node >= n) return;
    const float* x = X + (size_t)node * 256;
    float a[8];
#pragma unroll
    for (int i = 0; i < 8; i++) a[i] = 0.f;
#pragma unroll
    for (int t = 0; t < 8; t++) {
        int i = lane + 32 * t;
        float xv = x[i];
        a[0] = fmaf(xv, Wq[i * 2], a[0]);
        a[1] = fmaf(xv, Wq[i * 2 + 1], a[1]);
        a[2] = fmaf(xv, Wk[i * 2], a[2]);
        a[3] = fmaf(xv, Wk[i * 2 + 1], a[3]);
        a[4] = fmaf(xv, Wv[i * 2], a[4]);
        a[5] = fmaf(xv, Wv[i * 2 + 1], a[5]);
        a[6] = fmaf(xv, Ws[i * 2], a[6]);
        a[7] = fmaf(xv, Ws[i * 2 + 1], a[7]);
    }
#pragma unroll
    for (int i = 0; i < 8; i++) {
#pragma unroll
        for (int o = 16; o; o >>= 1) a[i] += __shfl_xor_sync(0xffffffffu, a[i], o);
    }
    if (lane == 0) {
        q[(size_t)node * 2 + 0] = a[0] + bq[0];
        q[(size_t)node * 2 + 1] = a[1] + bq[1];
        k[(size_t)node * 2 + 0] = a[2] + bk[0];
        k[(size_t)node * 2 + 1] = a[3] + bk[1];
        v[(size_t)node * 2 + 0] = a[4] + bv[0];
        v[(size_t)node * 2 + 1] = a[5] + bv[1];
        sOut[(size_t)node * 2 + 0] = a[6] + bs[0];
        sOut[(size_t)node * 2 + 1] = a[7] + bs[1];
    }
}

// ---------------- layer 3 fused finalize ----------------
__global__ void k_final3(const int* __restrict__ src,
                         const float* __restrict__ q2, const float* __restrict__ k2,
                         const float* __restrict__ v2, const float* __restrict__ s3,
                         float* __restrict__ out, int n, float scale) {
    int i = blockIdx.x * blockDim.x + threadIdx.x;
    if (i >= n) return;
    int s0 = g_rowptr[i], s1 = g_rowptr[i + 1];
    float q0 = q2[(size_t)i * 2 + 0], q1 = q2[(size_t)i * 2 + 1];
    float m = -INFINITY, den = 0.f, a0 = 0.f, a1 = 0.f;
    for (int j = s0; j < s1; j++) {
        int e = g_perm[j];
        int sv = src[e];
        float sc = (q0 * k2[(size_t)sv * 2] + q1 * k2[(size_t)sv * 2 + 1]) * scale;
        float nm = fmaxf(m, sc);
        float fa = __expf(m - nm);
        float w = __expf(sc - nm);
        den = den * fa + w;
        a0 = fmaf(w, v2[(size_t)sv * 2 + 0], a0 * fa);
        a1 = fmaf(w, v2[(size_t)sv * 2 + 1], a1 * fa);
        m = nm;
    }
    float inv = 1.f / (den + 1e-16f);
    a0 *= inv; a1 *= inv;
    float h0 = a0 + s3[(size_t)i * 2 + 0];
    float h1 = a1 + s3[(size_t)i * 2 + 1];
    float mx = fmaxf(h0, h1);
    float lse = mx + logf(expf(h0 - mx) + expf(h1 - mx));
    out[2 * i + 0] = h0 - lse;
    out[2 * i + 1] = h1 - lse;
}

// ---------------- launch ----------------
static inline int cdiv(int a, int b) { return (a + b - 1) / b; }

extern "C" void kernel_launch(void* const* d_in, const int* in_sizes, int n_in,
                              void* d_out, int out_size) {
    const float* x = (const float*)d_in[0];
    const int* ei = (const int*)d_in[1];
    const int N = in_sizes[0] / 128;
    const int E = in_sizes[1] / 2;
    const int* src = ei;
    const int* dst = ei + E;

    const float *Wq1 = (const float*)d_in[2],  *bq1 = (const float*)d_in[3];
    const float *Wk1 = (const float*)d_in[4],  *bk1 = (const float*)d_in[5];
    const float *Wv1 = (const float*)d_in[6],  *bv1 = (const float*)d_in[7];
    const float *Ws1 = (const float*)d_in[8],  *bs1 = (const float*)d_in[9];
    const float *Wq2 = (const float*)d_in[10], *bq2 = (const float*)d_in[11];
    const float *Wk2 = (const float*)d_in[12], *bk2 = (const float*)d_in[13];
    const float *Wv2 = (const float*)d_in[14], *bv2 = (const float*)d_in[15];
    const float *Ws2 = (const float*)d_in[16], *bs2 = (const float*)d_in[17];
    const float *Wq3 = (const float*)d_in[18], *bq3 = (const float*)d_in[19];
    const float *Wk3 = (const float*)d_in[20], *bk3 = (const float*)d_in[21];
    const float *Wv3 = (const float*)d_in[22], *bv3 = (const float*)d_in[23];
    const float *Ws3 = (const float*)d_in[24], *bs3 = (const float*)d_in[25];
    const float *ln1g = (const float*)d_in[26], *ln1b = (const float*)d_in[27];
    const float *ln2g = (const float*)d_in[28], *ln2b = (const float*)d_in[29];
    float* out = (float*)d_out;

    static float *yb = nullptr, *hb = nullptr;
    static bool cfg = false;
    static cudaStream_t s2;
    static cudaEvent_t evFork, evJoin;
    if (!cfg) {
        void* p;
        cudaGetSymbolAddress(&p, g_y); yb = (float*)p;
        cudaGetSymbolAddress(&p, g_h); hb = (float*)p;
        cudaStreamCreateWithFlags(&s2, cudaStreamNonBlocking);
        cudaEventCreateWithFlags(&evFork, cudaEventDisableTiming);
        cudaEventCreateWithFlags(&evJoin, cudaEventDisableTiming);
        cfg = true;
    }

    float* q = yb;
    float* k = yb + (size_t)NN * 512;
    float* v = yb + (size_t)NN * 1024;
    float* sOut = yb + (size_t)NN * 1536;

    const int TB = 256;

    // ---- fork: CSR build on s2, overlapped with layer-1 GEMM ----
    cudaEventRecord(evFork, 0);
    cudaStreamWaitEvent(s2, evFork, 0);

    int n1 = N + 1;
    int nch = cdiv(n1, 256);
    k_zero_rowptr<<<cdiv(n1, TB), TB, 0, s2>>>(n1);
    k_count<<<cdiv(E, TB), TB, 0, s2>>>(dst, E);
    k_block_sums<<<nch, 256, 0, s2>>>(n1);
    k_scan_chunks<<<1, 32, 0, s2>>>(nch);
    k_block_scan<<<nch, 256, 0, s2>>>(n1);
    k_cursor<<<cdiv(N, TB), TB, 0, s2>>>(N);
    k_scatter<<<cdiv(E, TB), TB, 0, s2>>>(dst, E);
    cudaEventRecord(evJoin, s2);

    // ================= layer 1: K=128, F=512, H=4, C=128 =================
    {
        int K = 128, F = 512;
        dim3 grid(4 * F / 128, cdiv(N, 128));
        k_mma4<<<grid, 256>>>(x, Wq1, bq1, q, Wk1, bk1, k, Wv1, bv1, v, Ws1, bs1, sOut, N, K, F);
        cudaStreamWaitEvent(0, evJoin, 0);
        k_edge<4, 128><<<cdiv(N * 32, TB), TB>>>(src, q, k, v, sOut, ln1g, ln1b, hb, N,
                                                 0.08838834764831845f);
    }
    // ================= layer 2: K=512, F=256, H=4, C=64 =================
    {
        int K = 512, F = 256;
        dim3 grid(4 * F / 128, cdiv(N, 128));
        k_mma4<<<grid, 256>>>(hb, Wq2, bq2, q, Wk2, bk2, k, Wv2, bv2, v, Ws2, bs2, sOut, N, K, F);
        k_edge<4, 64><<<cdiv(N * 32, TB), TB>>>(src, q, k, v, sOut, ln2g, ln2b, hb, N, 0.125f);
    }
    // ================= layer 3: K=256, F=2, H=1, C=2 =================
    {
        k_gemm3f<<<cdiv(N * 32, TB), TB>>>(hb, Wq3, bq3, Wk3, bk3, Wv3, bv3, Ws3, bs3,
                                           q, k, v, sOut, N);
        k_final3<<<cdiv(N, TB), TB>>>(src, q, k, v, sOut, out, N, 0.7071067811865475f);
    }
}

// round 15
// speedup vs baseline: 1.6382x; 1.0985x over previous
#include <cuda_runtime.h>
#include <cuda_bf16.h>
#include <cuda_fp16.h>
#include <cstdint>
#include <stdint.h>
#include <math.h>

#define NN 50000
#define EE 400000

// ---------------- scratch (device globals) ----------------
__device__ float g_y[(size_t)NN * 2048];     // q fp32 | s fp32 | k fp16 | v fp16 | l3 scratch
__device__ float g_h[(size_t)NN * 512];
__device__ int   g_rowptr[NN + 1];
__device__ int   g_cursor[NN];
__device__ int   g_perm[EE];
__device__ int   g_chunksum[256];

// ---------------- helpers ----------------
__device__ __forceinline__ uint32_t s2u(const void* p) {
    return (uint32_t)__cvta_generic_to_shared(p);
}
__device__ __forceinline__ void mma_bf16(float* c, const uint32_t* a, const uint32_t* b) {
    asm volatile(
        "mma.sync.aligned.m16n8k16.row.col.f32.bf16.bf16.f32 "
        "{%0,%1,%2,%3}, {%4,%5,%6,%7}, {%8,%9}, {%0,%1,%2,%3};"
        : "+f"(c[0]), "+f"(c[1]), "+f"(c[2]), "+f"(c[3])
        : "r"(a[0]), "r"(a[1]), "r"(a[2]), "r"(a[3]), "r"(b[0]), "r"(b[1]));
}
__device__ __forceinline__ void ldsm4(uint32_t addr, uint32_t& r0, uint32_t& r1,
                                      uint32_t& r2, uint32_t& r3) {
    asm volatile("ldmatrix.sync.aligned.m8n8.x4.shared.b16 {%0,%1,%2,%3}, [%4];"
                 : "=r"(r0), "=r"(r1), "=r"(r2), "=r"(r3) : "r"(addr));
}
__device__ __forceinline__ void ldsm4t(uint32_t addr, uint32_t& r0, uint32_t& r1,
                                       uint32_t& r2, uint32_t& r3) {
    asm volatile("ldmatrix.sync.aligned.m8n8.x4.trans.shared.b16 {%0,%1,%2,%3}, [%4];"
                 : "=r"(r0), "=r"(r1), "=r"(r2), "=r"(r3) : "r"(addr));
}
__device__ __forceinline__ void split2(float x, float y, uint32_t& hi, uint32_t& lo) {
    __nv_bfloat16 hx = __float2bfloat16_rn(x);
    __nv_bfloat16 hy = __float2bfloat16_rn(y);
    __nv_bfloat162 hh; hh.x = hx; hh.y = hy;
    hi = *(uint32_t*)&hh;
    __nv_bfloat162 ll;
    ll.x = __float2bfloat16_rn(x - __bfloat162float(hx));
    ll.y = __float2bfloat16_rn(y - __bfloat162float(hy));
    lo = *(uint32_t*)&ll;
}
__device__ __forceinline__ void unpack8(uint4 u, float* f) {
    float2 a = __half22float2(*(__half2*)&u.x);
    float2 b = __half22float2(*(__half2*)&u.y);
    float2 c = __half22float2(*(__half2*)&u.z);
    float2 d = __half22float2(*(__half2*)&u.w);
    f[0] = a.x; f[1] = a.y; f[2] = b.x; f[3] = b.y;
    f[4] = c.x; f[5] = c.y; f[6] = d.x; f[7] = d.y;
}

// ---------------- CSR build (by dst) ----------------
__global__ void k_zero_rowptr(int n) {
    int i = blockIdx.x * blockDim.x + threadIdx.x;
    if (i < n) g_rowptr[i] = 0;
}
__global__ void k_count(const int* __restrict__ dst, int E) {
    int e = blockIdx.x * blockDim.x + threadIdx.x;
    if (e < E) atomicAdd(&g_rowptr[dst[e] + 1], 1);
}
__global__ void k_block_sums(int n) {
    __shared__ int sh[256];
    int i = blockIdx.x * 256 + threadIdx.x;
    sh[threadIdx.x] = (i < n) ? g_rowptr[i] : 0;
    __syncthreads();
    for (int o = 128; o > 0; o >>= 1) {
        if (threadIdx.x < o) sh[threadIdx.x] += sh[threadIdx.x + o];
        __syncthreads();
    }
    if (threadIdx.x == 0) g_chunksum[blockIdx.x] = sh[0];
}
__global__ void k_scan_chunks(int nch) {
    if (threadIdx.x == 0 && blockIdx.x == 0) {
        int running = 0;
        for (int i = 0; i < nch; i++) {
            int t = g_chunksum[i];
            g_chunksum[i] = running;
            running += t;
        }
    }
}
__global__ void k_block_scan(int n) {
    __shared__ int sh[256];
    int i = blockIdx.x * 256 + threadIdx.x;
    int t = threadIdx.x;
    sh[t] = (i < n) ? g_rowptr[i] : 0;
    __syncthreads();
    for (int o = 1; o < 256; o <<= 1) {
        int v = sh[t];
        int u = (t >= o) ? sh[t - o] : 0;
        __syncthreads();
        sh[t] = v + u;
        __syncthreads();
    }
    if (i < n) g_rowptr[i] = sh[t] + g_chunksum[blockIdx.x];
}
__global__ void k_cursor(int n) {
    int i = blockIdx.x * blockDim.x + threadIdx.x;
    if (i < n) g_cursor[i] = g_rowptr[i];
}
__global__ void k_scatter(const int* __restrict__ dst, int E) {
    int e = blockIdx.x * blockDim.x + threadIdx.x;
    if (e < E) {
        int p = atomicAdd(&g_cursor[dst[e]], 1);
        g_perm[p] = e;
    }
}

// ---------------- BF16x3 tensor-core GEMM; k/v outputs stored fp16 ----------------
#define A_STR 40
#define B_STR 136

__global__ void __launch_bounds__(256) k_mma4(const float* __restrict__ Ag,
                                              const float* __restrict__ W0, const float* __restrict__ b0, float* __restrict__ o0,
                                              const float* __restrict__ W1, const float* __restrict__ b1, float* __restrict__ o1,
                                              const float* __restrict__ W2, const float* __restrict__ b2, float* __restrict__ o2,
                                              const float* __restrict__ W3, const float* __restrict__ b3, float* __restrict__ o3,
                                              int M, int K, int F) {
    __shared__ __align__(16) __nv_bfloat16 As_hi[128 * A_STR];
    __shared__ __align__(16) __nv_bfloat16 As_lo[128 * A_STR];
    __shared__ __align__(16) __nv_bfloat16 Bs_hi[32 * B_STR];
    __shared__ __align__(16) __nv_bfloat16 Bs_lo[32 * B_STR];

    int tid = threadIdx.x;
    int warp = tid >> 5, lane = tid & 31;
    int wm = warp >> 2;
    int wn = warp & 3;
    int gid = lane >> 2;
    int l4 = lane & 3;

    int nb = F / 128;
    int bsel = blockIdx.x / nb;
    int bn = blockIdx.x % nb;
    int bm = blockIdx.y;
    const float* W = bsel == 0 ? W0 : bsel == 1 ? W1 : bsel == 2 ? W2 : W3;
    const float* bias = bsel == 0 ? b0 : bsel == 1 ? b1 : bsel == 2 ? b2 : b3;
    float* outp = bsel == 0 ? o0 : bsel == 1 ? o1 : bsel == 2 ? o2 : o3;
    bool fp16out = (bsel == 1) || (bsel == 2);

    uint32_t* Ah32 = (uint32_t*)As_hi;
    uint32_t* Al32 = (uint32_t*)As_lo;
    uint32_t* Bh32 = (uint32_t*)Bs_hi;
    uint32_t* Bl32 = (uint32_t*)Bs_lo;
    uint32_t sAh = s2u(As_hi), sAl = s2u(As_lo);
    uint32_t sBh = s2u(Bs_hi), sBl = s2u(Bs_lo);

    int q = lane >> 3, r8 = lane & 7;
    int a_row_off = (q & 1) * 8 + r8;
    int a_col_off = (q >> 1) * 8;
    int b_k_off = (q & 1) * 8 + r8;
    int b_nblk = q >> 1;

    float acc[4][4][4];
#pragma unroll
    for (int i = 0; i < 4; i++)
#pragma unroll
        for (int j = 0; j < 4; j++)
#pragma unroll
            for (int r = 0; r < 4; r++) acc[i][j][r] = 0.f;

    for (int k0 = 0; k0 < K; k0 += 32) {
        __syncthreads();
#pragma unroll
        for (int i = 0; i < 4; i++) {
            int r = (tid >> 3) + i * 32;
            int fc = (tid & 7) * 4;
            int gr = bm * 128 + r;
            float4 v = make_float4(0.f, 0.f, 0.f, 0.f);
            if (gr < M) v = *(const float4*)(Ag + (size_t)gr * K + k0 + fc);
            uint32_t h0, l0, h1, l1;
            split2(v.x, v.y, h0, l0);
            split2(v.z, v.w, h1, l1);
            int base = r * (A_STR / 2) + fc / 2;
            Ah32[base] = h0; Ah32[base + 1] = h1;
            Al32[base] = l0; Al32[base + 1] = l1;
        }
        {
            int kk = tid >> 3;
            const float* Wrow = W + (size_t)(k0 + kk) * F + bn * 128;
#pragma unroll
            for (int i = 0; i < 4; i++) {
                int n = (tid & 7) * 4 + i * 32;
                float4 v = *(const float4*)(Wrow + n);
                uint32_t h0, l0, h1, l1;
                split2(v.x, v.y, h0, l0);
                split2(v.z, v.w, h1, l1);
                int base = kk * (B_STR / 2) + n / 2;
                Bh32[base] = h0; Bh32[base + 1] = h1;
                Bl32[base] = l0; Bl32[base + 1] = l1;
            }
        }
        __syncthreads();

#pragma unroll
        for (int ks = 0; ks < 32; ks += 16) {
            uint32_t ah[4][4], al[4][4], bh[4][2], bl[4][2];
#pragma unroll
            for (int tm = 0; tm < 4; tm++) {
                int mbase = wm * 64 + tm * 16;
                uint32_t off = (uint32_t)((mbase + a_row_off) * (A_STR * 2) +
                                          (ks + a_col_off) * 2);
                ldsm4(sAh + off, ah[tm][0], ah[tm][1], ah[tm][2], ah[tm][3]);
                ldsm4(sAl + off, al[tm][0], al[tm][1], al[tm][2], al[tm][3]);
            }
#pragma unroll
            for (int tnp = 0; tnp < 2; tnp++) {
                int n0 = wn * 32 + (tnp * 2 + b_nblk) * 8;
                uint32_t off = (uint32_t)((ks + b_k_off) * (B_STR * 2) + n0 * 2);
                ldsm4t(sBh + off, bh[2 * tnp][0], bh[2 * tnp][1],
                       bh[2 * tnp + 1][0], bh[2 * tnp + 1][1]);
                ldsm4t(sBl + off, bl[2 * tnp][0], bl[2 * tnp][1],
                       bl[2 * tnp + 1][0], bl[2 * tnp + 1][1]);
            }
#pragma unroll
            for (int tm = 0; tm < 4; tm++)
#pragma unroll
                for (int tn = 0; tn < 4; tn++) {
                    mma_bf16(acc[tm][tn], ah[tm], bh[tn]);
                    mma_bf16(acc[tm][tn], ah[tm], bl[tn]);
                    mma_bf16(acc[tm][tn], al[tm], bh[tn]);
                }
        }
    }

    // ---- epilogue: fp32 for q/s, fp16 for k/v ----
#pragma unroll
    for (int tm = 0; tm < 4; tm++) {
        int r0 = bm * 128 + wm * 64 + tm * 16 + gid;
        int r1 = r0 + 8;
#pragma unroll
        for (int tn = 0; tn < 4; tn++) {
            int c = bn * 128 + wn * 32 + tn * 8 + l4 * 2;
            float v00 = acc[tm][tn][0] + bias[c];
            float v01 = acc[tm][tn][1] + bias[c + 1];
            float v10 = acc[tm][tn][2] + bias[c];
            float v11 = acc[tm][tn][3] + bias[c + 1];
            if (fp16out) {
                __half* op = (__half*)outp;
                if (r0 < M) *(__half2*)(op + (size_t)r0 * F + c) = __floats2half2_rn(v00, v01);
                if (r1 < M) *(__half2*)(op + (size_t)r1 * F + c) = __floats2half2_rn(v10, v11);
            } else {
                if (r0 < M) {
                    outp[(size_t)r0 * F + c] = v00;
                    outp[(size_t)r0 * F + c + 1] = v01;
                }
                if (r1 < M) {
                    outp[(size_t)r1 * F + c] = v10;
                    outp[(size_t)r1 * F + c + 1] = v11;
                }
            }
        }
    }
}

// ---------------- FUSED edge phase: fp16 k/v gathers, online softmax, skip+LN+ELU --------
// chunk j = lane + 32*t covers channels [8j, 8j+8); head = 8j / C.
template <int H, int C>
__global__ void k_edge(const int* __restrict__ src,
                       const float* __restrict__ q, const __half* __restrict__ kk,
                       const __half* __restrict__ vv, const float* __restrict__ sskip,
                       const float* __restrict__ lng, const float* __restrict__ lnb,
                       float* __restrict__ outp, int n, float scale) {
    constexpr int F = H * C, TC = F / 256;   // uint4 chunks per lane
    int node = (blockIdx.x * blockDim.x + threadIdx.x) >> 5;
    int lane = threadIdx.x & 31;
    if (node >= n) return;
    int s0 = g_rowptr[node], s1 = g_rowptr[node + 1];

    // preload q chunks (channels 8j..8j+7)
    float qf[TC][8];
    const float4* qp = (const float4*)(q + (size_t)node * F);
#pragma unroll
    for (int t = 0; t < TC; t++) {
        int j = lane + 32 * t;
        float4 a = qp[2 * j], b = qp[2 * j + 1];
        qf[t][0] = a.x; qf[t][1] = a.y; qf[t][2] = a.z; qf[t][3] = a.w;
        qf[t][4] = b.x; qf[t][5] = b.y; qf[t][6] = b.z; qf[t][7] = b.w;
    }

    float m[H], den[H];
#pragma unroll
    for (int h = 0; h < H; h++) { m[h] = -INFINITY; den[h] = 0.f; }
    float acc[TC][8];
#pragma unroll
    for (int t = 0; t < TC; t++)
#pragma unroll
        for (int i = 0; i < 8; i++) acc[t][i] = 0.f;

    for (int j = s0; j < s1; j++) {
        int e = g_perm[j];
        int sv = src[e];
        const uint4* kp = (const uint4*)(kk + (size_t)sv * F);
        const uint4* vp = (const uint4*)(vv + (size_t)sv * F);

        float d[H];
#pragma unroll
        for (int h = 0; h < H; h++) d[h] = 0.f;
        float vr[TC][8];
#pragma unroll
        for (int t = 0; t < TC; t++) {
            int jj = lane + 32 * t;
            uint4 kc = kp[jj];
            uint4 vc = vp[jj];
            float kf[8];
            unpack8(kc, kf);
            unpack8(vc, vr[t]);
            float dd = qf[t][0] * kf[0] + qf[t][1] * kf[1] + qf[t][2] * kf[2] + qf[t][3] * kf[3]
                     + qf[t][4] * kf[4] + qf[t][5] * kf[5] + qf[t][6] * kf[6] + qf[t][7] * kf[7];
            if constexpr (C == 128) {
                // head = 2t + (lane>=16)
                if (lane < 16) d[2 * t] += dd;
                else d[2 * t + 1] += dd;
            } else {
                // head = lane/8
                int h = lane >> 3;
                d[0] += (h == 0) ? dd : 0.f;
                d[1] += (h == 1) ? dd : 0.f;
                d[2] += (h == 2) ? dd : 0.f;
                d[3] += (h == 3) ? dd : 0.f;
            }
        }
#pragma unroll
        for (int h = 0; h < H; h++) {
#pragma unroll
            for (int o = 16; o; o >>= 1) d[h] += __shfl_xor_sync(0xffffffffu, d[h], o);
            d[h] *= scale;
        }

        float fa[H], w[H];
#pragma unroll
        for (int h = 0; h < H; h++) {
            float nm = fmaxf(m[h], d[h]);
            fa[h] = __expf(m[h] - nm);
            w[h] = __expf(d[h] - nm);
            den[h] = den[h] * fa[h] + w[h];
            m[h] = nm;
        }
#pragma unroll
        for (int t = 0; t < TC; t++) {
            float f, ww;
            if constexpr (C == 128) {
                f = (lane < 16) ? fa[2 * t] : fa[2 * t + 1];
                ww = (lane < 16) ? w[2 * t] : w[2 * t + 1];
            } else {
                f = (lane < 8) ? fa[0] : (lane < 16) ? fa[1] : (lane < 24) ? fa[2] : fa[3];
                ww = (lane < 8) ? w[0] : (lane < 16) ? w[1] : (lane < 24) ? w[2] : w[3];
            }
#pragma unroll
            for (int i = 0; i < 8; i++)
                acc[t][i] = fmaf(ww, vr[t][i], acc[t][i] * f);
        }
    }

    // normalize
    float inv[H];
#pragma unroll
    for (int h = 0; h < H; h++) inv[h] = 1.f / (den[h] + 1e-16f);
#pragma unroll
    for (int t = 0; t < TC; t++) {
        float f;
        if constexpr (C == 128) f = (lane < 16) ? inv[2 * t] : inv[2 * t + 1];
        else f = (lane < 8) ? inv[0] : (lane < 16) ? inv[1] : (lane < 24) ? inv[2] : inv[3];
#pragma unroll
        for (int i = 0; i < 8; i++) acc[t][i] *= f;
    }

    // skip
    const float4* sp = (const float4*)(sskip + (size_t)node * F);
#pragma unroll
    for (int t = 0; t < TC; t++) {
        int j = lane + 32 * t;
        float4 a = sp[2 * j], b = sp[2 * j + 1];
        acc[t][0] += a.x; acc[t][1] += a.y; acc[t][2] += a.z; acc[t][3] += a.w;
        acc[t][4] += b.x; acc[t][5] += b.y; acc[t][6] += b.z; acc[t][7] += b.w;
    }

    // LayerNorm + ELU
    float s = 0.f;
#pragma unroll
    for (int t = 0; t < TC; t++)
#pragma unroll
        for (int i = 0; i < 8; i++) s += acc[t][i];
#pragma unroll
    for (int o = 16; o; o >>= 1) s += __shfl_xor_sync(0xffffffffu, s, o);
    float mean = s / (float)F;
    float vs = 0.f;
#pragma unroll
    for (int t = 0; t < TC; t++)
#pragma unroll
        for (int i = 0; i < 8; i++) {
            float dx = acc[t][i] - mean;
            vs = fmaf(dx, dx, vs);
        }
#pragma unroll
    for (int o = 16; o; o >>= 1) vs += __shfl_xor_sync(0xffffffffu, vs, o);
    float r = rsqrtf(vs / (float)F + 1e-5f);
    const float4* gp = (const float4*)lng;
    const float4* bp = (const float4*)lnb;
    float4* op = (float4*)(outp + (size_t)node * F);
#pragma unroll
    for (int t = 0; t < TC; t++) {
        int j = lane + 32 * t;
#pragma unroll
        for (int hlf = 0; hlf < 2; hlf++) {
            float4 g = gp[2 * j + hlf], bb = bp[2 * j + hlf], o4;
            float t0 = (acc[t][4 * hlf + 0] - mean) * r * g.x + bb.x;
            float t1 = (acc[t][4 * hlf + 1] - mean) * r * g.y + bb.y;
            float t2 = (acc[t][4 * hlf + 2] - mean) * r * g.z + bb.z;
            float t3 = (acc[t][4 * hlf + 3] - mean) * r * g.w + bb.w;
            o4.x = t0 > 0.f ? t0 : expm1f(t0);
            o4.y = t1 > 0.f ? t1 : expm1f(t1);
            o4.z = t2 > 0.f ? t2 : expm1f(t2);
            o4.w = t3 > 0.f ? t3 : expm1f(t3);
            op[2 * j + hlf] = o4;
        }
    }
}

// ---------------- layer 3: fused projection, warp per node ----------------
__global__ void k_gemm3f(const float* __restrict__ X,
                         const float* __restrict__ Wq, const float* __restrict__ bq,
                         const float* __restrict__ Wk, const float* __restrict__ bk,
                         const float* __restrict__ Wv, const float* __restrict__ bv,
                         const float* __restrict__ Ws, const float* __restrict__ bs,
                         float* __restrict__ q, float* __restrict__ k,
                         float* __restrict__ v, float* __restrict__ sOut, int n) {
    int node = (blockIdx.x * blockDim.x + threadIdx.x) >> 5;
    int lane = threadIdx.x & 31;
    if (node >= n) return;
    const float* x = X + (size_t)node * 256;
    float a[8];
#pragma unroll
    for (int i = 0; i < 8; i++) a[i] = 0.f;
#pragma unroll
    for (int t = 0; t < 8; t++) {
        int i = lane + 32 * t;
        float xv = x[i];
        a[0] = fmaf(xv, Wq[i * 2], a[0]);
        a[1] = fmaf(xv, Wq[i * 2 + 1], a[1]);
        a[2] = fmaf(xv, Wk[i * 2], a[2]);
        a[3] = fmaf(xv, Wk[i * 2 + 1], a[3]);
        a[4] = fmaf(xv, Wv[i * 2], a[4]);
        a[5] = fmaf(xv, Wv[i * 2 + 1], a[5]);
        a[6] = fmaf(xv, Ws[i * 2], a[6]);
        a[7] = fmaf(xv, Ws[i * 2 + 1], a[7]);
    }
#pragma unroll
    for (int i = 0; i < 8; i++) {
#pragma unroll
        for (int o = 16; o; o >>= 1) a[i] += __shfl_xor_sync(0xffffffffu, a[i], o);
    }
    if (lane == 0) {
        q[(size_t)node * 2 + 0] = a[0] + bq[0];
        q[(size_t)node * 2 + 1] = a[1] + bq[1];
        k[(size_t)node * 2 + 0] = a[2] + bk[0];
        k[(size_t)node * 2 + 1] = a[3] + bk[1];
        v[(size_t)node * 2 + 0] = a[4] + bv[0];
        v[(size_t)node * 2 + 1] = a[5] + bv[1];
        sOut[(size_t)node * 2 + 0] = a[6] + bs[0];
        sOut[(size_t)node * 2 + 1] = a[7] + bs[1];
    }
}

// ---------------- layer 3 fused finalize ----------------
__global__ void k_final3(const int* __restrict__ src,
                         const float* __restrict__ q2, const float* __restrict__ k2,
                         const float* __restrict__ v2, const float* __restrict__ s3,
                         float* __restrict__ out, int n, float scale) {
    int i = blockIdx.x * blockDim.x + threadIdx.x;
    if (i >= n) return;
    int s0 = g_rowptr[i], s1 = g_rowptr[i + 1];
    float q0 = q2[(size_t)i * 2 + 0], q1 = q2[(size_t)i * 2 + 1];
    float m = -INFINITY, den = 0.f, a0 = 0.f, a1 = 0.f;
    for (int j = s0; j < s1; j++) {
        int e = g_perm[j];
        int sv = src[e];
        float sc = (q0 * k2[(size_t)sv * 2] + q1 * k2[(size_t)sv * 2 + 1]) * scale;
        float nm = fmaxf(m, sc);
        float fa = __expf(m - nm);
        float w = __expf(sc - nm);
        den = den * fa + w;
        a0 = fmaf(w, v2[(size_t)sv * 2 + 0], a0 * fa);
        a1 = fmaf(w, v2[(size_t)sv * 2 + 1], a1 * fa);
        m = nm;
    }
    float inv = 1.f / (den + 1e-16f);
    a0 *= inv; a1 *= inv;
    float h0 = a0 + s3[(size_t)i * 2 + 0];
    float h1 = a1 + s3[(size_t)i * 2 + 1];
    float mx = fmaxf(h0, h1);
    float lse = mx + logf(expf(h0 - mx) + expf(h1 - mx));
    out[2 * i + 0] = h0 - lse;
    out[2 * i + 1] = h1 - lse;
}

// ---------------- launch ----------------
static inline int cdiv(int a, int b) { return (a + b - 1) / b; }

extern "C" void kernel_launch(void* const* d_in, const int* in_sizes, int n_in,
                              void* d_out, int out_size) {
    const float* x = (const float*)d_in[0];
    const int* ei = (const int*)d_in[1];
    const int N = in_sizes[0] / 128;
    const int E = in_sizes[1] / 2;
    const int* src = ei;
    const int* dst = ei + E;

    const float *Wq1 = (const float*)d_in[2],  *bq1 = (const float*)d_in[3];
    const float *Wk1 = (const float*)d_in[4],  *bk1 = (const float*)d_in[5];
    const float *Wv1 = (const float*)d_in[6],  *bv1 = (const float*)d_in[7];
    const float *Ws1 = (const float*)d_in[8],  *bs1 = (const float*)d_in[9];
    const float *Wq2 = (const float*)d_in[10], *bq2 = (const float*)d_in[11];
    const float *Wk2 = (const float*)d_in[12], *bk2 = (const float*)d_in[13];
    const float *Wv2 = (const float*)d_in[14], *bv2 = (const float*)d_in[15];
    const float *Ws2 = (const float*)d_in[16], *bs2 = (const float*)d_in[17];
    const float *Wq3 = (const float*)d_in[18], *bq3 = (const float*)d_in[19];
    const float *Wk3 = (const float*)d_in[20], *bk3 = (const float*)d_in[21];
    const float *Wv3 = (const float*)d_in[22], *bv3 = (const float*)d_in[23];
    const float *Ws3 = (const float*)d_in[24], *bs3 = (const float*)d_in[25];
    const float *ln1g = (const float*)d_in[26], *ln1b = (const float*)d_in[27];
    const float *ln2g = (const float*)d_in[28], *ln2b = (const float*)d_in[29];
    float* out = (float*)d_out;

    static float *yb = nullptr, *hb = nullptr;
    static bool cfg = false;
    static cudaStream_t s2;
    static cudaEvent_t evFork, evJoin;
    if (!cfg) {
        void* p;
        cudaGetSymbolAddress(&p, g_y); yb = (float*)p;
        cudaGetSymbolAddress(&p, g_h); hb = (float*)p;
        cudaStreamCreateWithFlags(&s2, cudaStreamNonBlocking);
        cudaEventCreateWithFlags(&evFork, cudaEventDisableTiming);
        cudaEventCreateWithFlags(&evJoin, cudaEventDisableTiming);
        cfg = true;
    }

    // buffer carve-out (floats): q fp32 [0, 512N) | s fp32 [512N, 1024N)
    // k fp16 at 1024N (512N halves = 256N floats) | v fp16 at 1280N
    // layer-3 scratch at 1536N
    float* q = yb;
    float* sOut = yb + (size_t)NN * 512;
    __half* kh = (__half*)(yb + (size_t)NN * 1024);
    __half* vh = (__half*)(yb + (size_t)NN * 1280);
    float* q3 = yb + (size_t)NN * 1536;
    float* k3 = q3 + (size_t)NN * 2;
    float* v3 = k3 + (size_t)NN * 2;
    float* s3 = v3 + (size_t)NN * 2;

    const int TB = 256;

    // ---- fork: CSR build on s2, overlapped with layer-1 GEMM ----
    cudaEventRecord(evFork, 0);
    cudaStreamWaitEvent(s2, evFork, 0);

    int n1 = N + 1;
    int nch = cdiv(n1, 256);
    k_zero_rowptr<<<cdiv(n1, TB), TB, 0, s2>>>(n1);
    k_count<<<cdiv(E, TB), TB, 0, s2>>>(dst, E);
    k_block_sums<<<nch, 256, 0, s2>>>(n1);
    k_scan_chunks<<<1, 32, 0, s2>>>(nch);
    k_block_scan<<<nch, 256, 0, s2>>>(n1);
    k_cursor<<<cdiv(N, TB), TB, 0, s2>>>(N);
    k_scatter<<<cdiv(E, TB), TB, 0, s2>>>(dst, E);
    cudaEventRecord(evJoin, s2);

    // ================= layer 1: K=128, F=512, H=4, C=128 =================
    {
        int K = 128, F = 512;
        dim3 grid(4 * F / 128, cdiv(N, 128));
        k_mma4<<<grid, 256>>>(x, Wq1, bq1, q, Wk1, bk1, (float*)kh, Wv1, bv1, (float*)vh,
                              Ws1, bs1, sOut, N, K, F);
        cudaStreamWaitEvent(0, evJoin, 0);
        k_edge<4, 128><<<cdiv(N * 32, TB), TB>>>(src, q, kh, vh, sOut, ln1g, ln1b, hb, N,
                                                 0.08838834764831845f);
    }
    // ================= layer 2: K=512, F=256, H=4, C=64 =================
    {
        int K = 512, F = 256;
        dim3 grid(4 * F / 128, cdiv(N, 128));
        k_mma4<<<grid, 256>>>(hb, Wq2, bq2, q, Wk2, bk2, (float*)kh, Wv2, bv2, (float*)vh,
                              Ws2, bs2, sOut, N, K, F);
        k_edge<4, 64><<<cdiv(N * 32, TB), TB>>>(src, q, kh, vh, sOut, ln2g, ln2b, hb, N, 0.125f);
    }
    // ================= layer 3: K=256, F=2, H=1, C=2 =================
    {
        k_gemm3f<<<cdiv(N * 32, TB), TB>>>(hb, Wq3, bq3, Wk3, bk3, Wv3, bv3, Ws3, bs3,
                                           q3, k3, v3, s3, N);
        k_final3<<<cdiv(N, TB), TB>>>(src, q3, k3, v3, s3, out, N, 0.7071067811865475f);
    }
}

// round 16
// speedup vs baseline: 1.6761x; 1.0231x over previous
#include <cuda_runtime.h>
#include <cuda_bf16.h>
#include <cuda_fp16.h>
#include <cstdint>
#include <stdint.h>
#include <math.h>

#define NN 50000
#define EE 400000

// ---------------- scratch (device globals) ----------------
__device__ float g_y[(size_t)NN * 2048];     // q fp32 | s fp32 | k fp16 | v fp16 | l3 scratch
__device__ float g_h[(size_t)NN * 512];
__device__ int   g_rowptr[NN + 1];
__device__ int   g_cursor[NN];
__device__ int   g_perm[EE];
__device__ int   g_chunksum[256];

// ---------------- helpers ----------------
__device__ __forceinline__ uint32_t s2u(const void* p) {
    return (uint32_t)__cvta_generic_to_shared(p);
}
__device__ __forceinline__ void mma_bf16(float* c, const uint32_t* a, const uint32_t* b) {
    asm volatile(
        "mma.sync.aligned.m16n8k16.row.col.f32.bf16.bf16.f32 "
        "{%0,%1,%2,%3}, {%4,%5,%6,%7}, {%8,%9}, {%0,%1,%2,%3};"
        : "+f"(c[0]), "+f"(c[1]), "+f"(c[2]), "+f"(c[3])
        : "r"(a[0]), "r"(a[1]), "r"(a[2]), "r"(a[3]), "r"(b[0]), "r"(b[1]));
}
__device__ __forceinline__ void ldsm4(uint32_t addr, uint32_t& r0, uint32_t& r1,
                                      uint32_t& r2, uint32_t& r3) {
    asm volatile("ldmatrix.sync.aligned.m8n8.x4.shared.b16 {%0,%1,%2,%3}, [%4];"
                 : "=r"(r0), "=r"(r1), "=r"(r2), "=r"(r3) : "r"(addr));
}
__device__ __forceinline__ void ldsm4t(uint32_t addr, uint32_t& r0, uint32_t& r1,
                                       uint32_t& r2, uint32_t& r3) {
    asm volatile("ldmatrix.sync.aligned.m8n8.x4.trans.shared.b16 {%0,%1,%2,%3}, [%4];"
                 : "=r"(r0), "=r"(r1), "=r"(r2), "=r"(r3) : "r"(addr));
}
__device__ __forceinline__ void split2(float x, float y, uint32_t& hi, uint32_t& lo) {
    __nv_bfloat16 hx = __float2bfloat16_rn(x);
    __nv_bfloat16 hy = __float2bfloat16_rn(y);
    __nv_bfloat162 hh; hh.x = hx; hh.y = hy;
    hi = *(uint32_t*)&hh;
    __nv_bfloat162 ll;
    ll.x = __float2bfloat16_rn(x - __bfloat162float(hx));
    ll.y = __float2bfloat16_rn(y - __bfloat162float(hy));
    lo = *(uint32_t*)&ll;
}
__device__ __forceinline__ void unpack8(uint4 u, float* f) {
    float2 a = __half22float2(*(__half2*)&u.x);
    float2 b = __half22float2(*(__half2*)&u.y);
    float2 c = __half22float2(*(__half2*)&u.z);
    float2 d = __half22float2(*(__half2*)&u.w);
    f[0] = a.x; f[1] = a.y; f[2] = b.x; f[3] = b.y;
    f[4] = c.x; f[5] = c.y; f[6] = d.x; f[7] = d.y;
}

// ---------------- CSR build (by dst) ----------------
__global__ void k_zero_rowptr(int n) {
    int i = blockIdx.x * blockDim.x + threadIdx.x;
    if (i < n) g_rowptr[i] = 0;
}
__global__ void k_count(const int* __restrict__ dst, int E) {
    int e = blockIdx.x * blockDim.x + threadIdx.x;
    if (e < E) atomicAdd(&g_rowptr[dst[e] + 1], 1);
}
__global__ void k_block_sums(int n) {
    __shared__ int sh[256];
    int i = blockIdx.x * 256 + threadIdx.x;
    sh[threadIdx.x] = (i < n) ? g_rowptr[i] : 0;
    __syncthreads();
    for (int o = 128; o > 0; o >>= 1) {
        if (threadIdx.x < o) sh[threadIdx.x] += sh[threadIdx.x + o];
        __syncthreads();
    }
    if (threadIdx.x == 0) g_chunksum[blockIdx.x] = sh[0];
}
__global__ void k_scan_chunks(int nch) {
    if (threadIdx.x == 0 && blockIdx.x == 0) {
        int running = 0;
        for (int i = 0; i < nch; i++) {
            int t = g_chunksum[i];
            g_chunksum[i] = running;
            running += t;
        }
    }
}
__global__ void k_block_scan(int n) {
    __shared__ int sh[256];
    int i = blockIdx.x * 256 + threadIdx.x;
    int t = threadIdx.x;
    sh[t] = (i < n) ? g_rowptr[i] : 0;
    __syncthreads();
    for (int o = 1; o < 256; o <<= 1) {
        int v = sh[t];
        int u = (t >= o) ? sh[t - o] : 0;
        __syncthreads();
        sh[t] = v + u;
        __syncthreads();
    }
    if (i < n) g_rowptr[i] = sh[t] + g_chunksum[blockIdx.x];
}
__global__ void k_cursor(int n) {
    int i = blockIdx.x * blockDim.x + threadIdx.x;
    if (i < n) g_cursor[i] = g_rowptr[i];
}
__global__ void k_scatter(const int* __restrict__ dst, int E) {
    int e = blockIdx.x * blockDim.x + threadIdx.x;
    if (e < E) {
        int p = atomicAdd(&g_cursor[dst[e]], 1);
        g_perm[p] = e;
    }
}

// ---------------- BF16x3 tensor-core GEMM; k/v outputs stored fp16 ----------------
#define A_STR 40
#define B_STR 136

__global__ void __launch_bounds__(256) k_mma4(const float* __restrict__ Ag,
                                              const float* __restrict__ W0, const float* __restrict__ b0, float* __restrict__ o0,
                                              const float* __restrict__ W1, const float* __restrict__ b1, float* __restrict__ o1,
                                              const float* __restrict__ W2, const float* __restrict__ b2, float* __restrict__ o2,
                                              const float* __restrict__ W3, const float* __restrict__ b3, float* __restrict__ o3,
                                              int M, int K, int F) {
    __shared__ __align__(16) __nv_bfloat16 As_hi[128 * A_STR];
    __shared__ __align__(16) __nv_bfloat16 As_lo[128 * A_STR];
    __shared__ __align__(16) __nv_bfloat16 Bs_hi[32 * B_STR];
    __shared__ __align__(16) __nv_bfloat16 Bs_lo[32 * B_STR];

    int tid = threadIdx.x;
    int warp = tid >> 5, lane = tid & 31;
    int wm = warp >> 2;
    int wn = warp & 3;
    int gid = lane >> 2;
    int l4 = lane & 3;

    int nb = F / 128;
    int bsel = blockIdx.x / nb;
    int bn = blockIdx.x % nb;
    int bm = blockIdx.y;
    const float* W = bsel == 0 ? W0 : bsel == 1 ? W1 : bsel == 2 ? W2 : W3;
    const float* bias = bsel == 0 ? b0 : bsel == 1 ? b1 : bsel == 2 ? b2 : b3;
    float* outp = bsel == 0 ? o0 : bsel == 1 ? o1 : bsel == 2 ? o2 : o3;
    bool fp16out = (bsel == 1) || (bsel == 2);

    uint32_t* Ah32 = (uint32_t*)As_hi;
    uint32_t* Al32 = (uint32_t*)As_lo;
    uint32_t* Bh32 = (uint32_t*)Bs_hi;
    uint32_t* Bl32 = (uint32_t*)Bs_lo;
    uint32_t sAh = s2u(As_hi), sAl = s2u(As_lo);
    uint32_t sBh = s2u(Bs_hi), sBl = s2u(Bs_lo);

    int q = lane >> 3, r8 = lane & 7;
    int a_row_off = (q & 1) * 8 + r8;
    int a_col_off = (q >> 1) * 8;
    int b_k_off = (q & 1) * 8 + r8;
    int b_nblk = q >> 1;

    float acc[4][4][4];
#pragma unroll
    for (int i = 0; i < 4; i++)
#pragma unroll
        for (int j = 0; j < 4; j++)
#pragma unroll
            for (int r = 0; r < 4; r++) acc[i][j][r] = 0.f;

    for (int k0 = 0; k0 < K; k0 += 32) {
        __syncthreads();
#pragma unroll
        for (int i = 0; i < 4; i++) {
            int r = (tid >> 3) + i * 32;
            int fc = (tid & 7) * 4;
            int gr = bm * 128 + r;
            float4 v = make_float4(0.f, 0.f, 0.f, 0.f);
            if (gr < M) v = *(const float4*)(Ag + (size_t)gr * K + k0 + fc);
            uint32_t h0, l0, h1, l1;
            split2(v.x, v.y, h0, l0);
            split2(v.z, v.w, h1, l1);
            int base = r * (A_STR / 2) + fc / 2;
            Ah32[base] = h0; Ah32[base + 1] = h1;
            Al32[base] = l0; Al32[base + 1] = l1;
        }
        {
            int kk = tid >> 3;
            const float* Wrow = W + (size_t)(k0 + kk) * F + bn * 128;
#pragma unroll
            for (int i = 0; i < 4; i++) {
                int n = (tid & 7) * 4 + i * 32;
                float4 v = *(const float4*)(Wrow + n);
                uint32_t h0, l0, h1, l1;
                split2(v.x, v.y, h0, l0);
                split2(v.z, v.w, h1, l1);
                int base = kk * (B_STR / 2) + n / 2;
                Bh32[base] = h0; Bh32[base + 1] = h1;
                Bl32[base] = l0; Bl32[base + 1] = l1;
            }
        }
        __syncthreads();

#pragma unroll
        for (int ks = 0; ks < 32; ks += 16) {
            uint32_t ah[4][4], al[4][4], bh[4][2], bl[4][2];
#pragma unroll
            for (int tm = 0; tm < 4; tm++) {
                int mbase = wm * 64 + tm * 16;
                uint32_t off = (uint32_t)((mbase + a_row_off) * (A_STR * 2) +
                                          (ks + a_col_off) * 2);
                ldsm4(sAh + off, ah[tm][0], ah[tm][1], ah[tm][2], ah[tm][3]);
                ldsm4(sAl + off, al[tm][0], al[tm][1], al[tm][2], al[tm][3]);
            }
#pragma unroll
            for (int tnp = 0; tnp < 2; tnp++) {
                int n0 = wn * 32 + (tnp * 2 + b_nblk) * 8;
                uint32_t off = (uint32_t)((ks + b_k_off) * (B_STR * 2) + n0 * 2);
                ldsm4t(sBh + off, bh[2 * tnp][0], bh[2 * tnp][1],
                       bh[2 * tnp + 1][0], bh[2 * tnp + 1][1]);
                ldsm4t(sBl + off, bl[2 * tnp][0], bl[2 * tnp][1],
                       bl[2 * tnp + 1][0], bl[2 * tnp + 1][1]);
            }
#pragma unroll
            for (int tm = 0; tm < 4; tm++)
#pragma unroll
                for (int tn = 0; tn < 4; tn++) {
                    mma_bf16(acc[tm][tn], ah[tm], bh[tn]);
                    mma_bf16(acc[tm][tn], ah[tm], bl[tn]);
                    mma_bf16(acc[tm][tn], al[tm], bh[tn]);
                }
        }
    }

#pragma unroll
    for (int tm = 0; tm < 4; tm++) {
        int r0 = bm * 128 + wm * 64 + tm * 16 + gid;
        int r1 = r0 + 8;
#pragma unroll
        for (int tn = 0; tn < 4; tn++) {
            int c = bn * 128 + wn * 32 + tn * 8 + l4 * 2;
            float v00 = acc[tm][tn][0] + bias[c];
            float v01 = acc[tm][tn][1] + bias[c + 1];
            float v10 = acc[tm][tn][2] + bias[c];
            float v11 = acc[tm][tn][3] + bias[c + 1];
            if (fp16out) {
                __half* op = (__half*)outp;
                if (r0 < M) *(__half2*)(op + (size_t)r0 * F + c) = __floats2half2_rn(v00, v01);
                if (r1 < M) *(__half2*)(op + (size_t)r1 * F + c) = __floats2half2_rn(v10, v11);
            } else {
                if (r0 < M) {
                    outp[(size_t)r0 * F + c] = v00;
                    outp[(size_t)r0 * F + c + 1] = v01;
                }
                if (r1 < M) {
                    outp[(size_t)r1 * F + c] = v10;
                    outp[(size_t)r1 * F + c + 1] = v11;
                }
            }
        }
    }
}

// ---------------- FUSED edge phase: 2x-unrolled edge loop, fp16 k/v gathers --------------
template <int H, int C>
__global__ void k_edge(const int* __restrict__ src,
                       const float* __restrict__ q, const __half* __restrict__ kk,
                       const __half* __restrict__ vv, const float* __restrict__ sskip,
                       const float* __restrict__ lng, const float* __restrict__ lnb,
                       float* __restrict__ outp, int n, float scale) {
    constexpr int F = H * C, TC = F / 256;   // uint4 chunks per lane
    int node = (blockIdx.x * blockDim.x + threadIdx.x) >> 5;
    int lane = threadIdx.x & 31;
    if (node >= n) return;
    int s0 = g_rowptr[node], s1 = g_rowptr[node + 1];

    float qf[TC][8];
    const float4* qp = (const float4*)(q + (size_t)node * F);
#pragma unroll
    for (int t = 0; t < TC; t++) {
        int j = lane + 32 * t;
        float4 a = qp[2 * j], b = qp[2 * j + 1];
        qf[t][0] = a.x; qf[t][1] = a.y; qf[t][2] = a.z; qf[t][3] = a.w;
        qf[t][4] = b.x; qf[t][5] = b.y; qf[t][6] = b.z; qf[t][7] = b.w;
    }

    float m[H], den[H];
#pragma unroll
    for (int h = 0; h < H; h++) { m[h] = -INFINITY; den[h] = 0.f; }
    float acc[TC][8];
#pragma unroll
    for (int t = 0; t < TC; t++)
#pragma unroll
        for (int i = 0; i < 8; i++) acc[t][i] = 0.f;

    // helpers as lambdas
    auto dotChunk = [&](const float* kf, int t, float* d) {
        float dd = qf[t][0] * kf[0] + qf[t][1] * kf[1] + qf[t][2] * kf[2] + qf[t][3] * kf[3]
                 + qf[t][4] * kf[4] + qf[t][5] * kf[5] + qf[t][6] * kf[6] + qf[t][7] * kf[7];
        if constexpr (C == 128) {
            if (lane < 16) d[2 * t] += dd;
            else d[2 * t + 1] += dd;
        } else {
            int h = lane >> 3;
            d[0] += (h == 0) ? dd : 0.f;
            d[1] += (h == 1) ? dd : 0.f;
            d[2] += (h == 2) ? dd : 0.f;
            d[3] += (h == 3) ? dd : 0.f;
        }
    };
    auto update = [&](const float (*vr)[8], const float* d) {
        float fa[H], w[H];
#pragma unroll
        for (int h = 0; h < H; h++) {
            float nm = fmaxf(m[h], d[h]);
            fa[h] = __expf(m[h] - nm);
            w[h] = __expf(d[h] - nm);
            den[h] = den[h] * fa[h] + w[h];
            m[h] = nm;
        }
#pragma unroll
        for (int t = 0; t < TC; t++) {
            float f, ww;
            if constexpr (C == 128) {
                f = (lane < 16) ? fa[2 * t] : fa[2 * t + 1];
                ww = (lane < 16) ? w[2 * t] : w[2 * t + 1];
            } else {
                f = (lane < 8) ? fa[0] : (lane < 16) ? fa[1] : (lane < 24) ? fa[2] : fa[3];
                ww = (lane < 8) ? w[0] : (lane < 16) ? w[1] : (lane < 24) ? w[2] : w[3];
            }
#pragma unroll
            for (int i = 0; i < 8; i++)
                acc[t][i] = fmaf(ww, vr[t][i], acc[t][i] * f);
        }
    };

    int j = s0;
    for (; j + 1 < s1; j += 2) {
        int e0 = g_perm[j], e1 = g_perm[j + 1];
        int sv0 = src[e0], sv1 = src[e1];
        const uint4* kp0 = (const uint4*)(kk + (size_t)sv0 * F);
        const uint4* vp0 = (const uint4*)(vv + (size_t)sv0 * F);
        const uint4* kp1 = (const uint4*)(kk + (size_t)sv1 * F);
        const uint4* vp1 = (const uint4*)(vv + (size_t)sv1 * F);

        // issue all loads for both edges first (max MLP)
        uint4 kc0[TC], vc0[TC], kc1[TC], vc1[TC];
#pragma unroll
        for (int t = 0; t < TC; t++) {
            int jj = lane + 32 * t;
            kc0[t] = kp0[jj]; vc0[t] = vp0[jj];
            kc1[t] = kp1[jj]; vc1[t] = vp1[jj];
        }

        float d0[H], d1[H];
#pragma unroll
        for (int h = 0; h < H; h++) { d0[h] = 0.f; d1[h] = 0.f; }
        float vr0[TC][8], vr1[TC][8];
#pragma unroll
        for (int t = 0; t < TC; t++) {
            float kf[8];
            unpack8(kc0[t], kf);
            unpack8(vc0[t], vr0[t]);
            dotChunk(kf, t, d0);
            unpack8(kc1[t], kf);
            unpack8(vc1[t], vr1[t]);
            dotChunk(kf, t, d1);
        }
        // interleaved independent reductions
#pragma unroll
        for (int o = 16; o; o >>= 1) {
#pragma unroll
            for (int h = 0; h < H; h++) {
                d0[h] += __shfl_xor_sync(0xffffffffu, d0[h], o);
                d1[h] += __shfl_xor_sync(0xffffffffu, d1[h], o);
            }
        }
#pragma unroll
        for (int h = 0; h < H; h++) { d0[h] *= scale; d1[h] *= scale; }

        update(vr0, d0);
        update(vr1, d1);
    }
    // tail edge
    if (j < s1) {
        int e = g_perm[j];
        int sv = src[e];
        const uint4* kp = (const uint4*)(kk + (size_t)sv * F);
        const uint4* vp = (const uint4*)(vv + (size_t)sv * F);
        float d[H];
#pragma unroll
        for (int h = 0; h < H; h++) d[h] = 0.f;
        float vr[TC][8];
#pragma unroll
        for (int t = 0; t < TC; t++) {
            int jj = lane + 32 * t;
            float kf[8];
            unpack8(kp[jj], kf);
            unpack8(vp[jj], vr[t]);
            dotChunk(kf, t, d);
        }
#pragma unroll
        for (int h = 0; h < H; h++) {
#pragma unroll
            for (int o = 16; o; o >>= 1) d[h] += __shfl_xor_sync(0xffffffffu, d[h], o);
            d[h] *= scale;
        }
        update(vr, d);
    }

    // normalize
    float inv[H];
#pragma unroll
    for (int h = 0; h < H; h++) inv[h] = 1.f / (den[h] + 1e-16f);
#pragma unroll
    for (int t = 0; t < TC; t++) {
        float f;
        if constexpr (C == 128) f = (lane < 16) ? inv[2 * t] : inv[2 * t + 1];
        else f = (lane < 8) ? inv[0] : (lane < 16) ? inv[1] : (lane < 24) ? inv[2] : inv[3];
#pragma unroll
        for (int i = 0; i < 8; i++) acc[t][i] *= f;
    }

    // skip
    const float4* sp = (const float4*)(sskip + (size_t)node * F);
#pragma unroll
    for (int t = 0; t < TC; t++) {
        int jj = lane + 32 * t;
        float4 a = sp[2 * jj], b = sp[2 * jj + 1];
        acc[t][0] += a.x; acc[t][1] += a.y; acc[t][2] += a.z; acc[t][3] += a.w;
        acc[t][4] += b.x; acc[t][5] += b.y; acc[t][6] += b.z; acc[t][7] += b.w;
    }

    // LayerNorm + ELU
    float s = 0.f;
#pragma unroll
    for (int t = 0; t < TC; t++)
#pragma unroll
        for (int i = 0; i < 8; i++) s += acc[t][i];
#pragma unroll
    for (int o = 16; o; o >>= 1) s += __shfl_xor_sync(0xffffffffu, s, o);
    float mean = s / (float)F;
    float vs = 0.f;
#pragma unroll
    for (int t = 0; t < TC; t++)
#pragma unroll
        for (int i = 0; i < 8; i++) {
            float dx = acc[t][i] - mean;
            vs = fmaf(dx, dx, vs);
        }
#pragma unroll
    for (int o = 16; o; o >>= 1) vs += __shfl_xor_sync(0xffffffffu, vs, o);
    float r = rsqrtf(vs / (float)F + 1e-5f);
    const float4* gp = (const float4*)lng;
    const float4* bp = (const float4*)lnb;
    float4* op = (float4*)(outp + (size_t)node * F);
#pragma unroll
    for (int t = 0; t < TC; t++) {
        int jj = lane + 32 * t;
#pragma unroll
        for (int hlf = 0; hlf < 2; hlf++) {
            float4 g = gp[2 * jj + hlf], bb = bp[2 * jj + hlf], o4;
            float t0 = (acc[t][4 * hlf + 0] - mean) * r * g.x + bb.x;
            float t1 = (acc[t][4 * hlf + 1] - mean) * r * g.y + bb.y;
            float t2 = (acc[t][4 * hlf + 2] - mean) * r * g.z + bb.z;
            float t3 = (acc[t][4 * hlf + 3] - mean) * r * g.w + bb.w;
            o4.x = t0 > 0.f ? t0 : expm1f(t0);
            o4.y = t1 > 0.f ? t1 : expm1f(t1);
            o4.z = t2 > 0.f ? t2 : expm1f(t2);
            o4.w = t3 > 0.f ? t3 : expm1f(t3);
            op[2 * jj + hlf] = o4;
        }
    }
}

// ---------------- layer 3: fused projection, warp per node ----------------
__global__ void k_gemm3f(const float* __restrict__ X,
                         const float* __restrict__ Wq, const float* __restrict__ bq,
                         const float* __restrict__ Wk, const float* __restrict__ bk,
                         const float* __restrict__ Wv, const float* __restrict__ bv,
                         const float* __restrict__ Ws, const float* __restrict__ bs,
                         float* __restrict__ q, float* __restrict__ k,
                         float* __restrict__ v, float* __restrict__ sOut, int n) {
    int node = (blockIdx.x * blockDim.x + threadIdx.x) >> 5;
    int lane = threadIdx.x & 31;
    if (node >= n) return;
    const float* x = X + (size_t)node * 256;
    float a[8];
#pragma unroll
    for (int i = 0; i < 8; i++) a[i] = 0.f;
#pragma unroll
    for (int t = 0; t < 8; t++) {
        int i = lane + 32 * t;
        float xv = x[i];
        a[0] = fmaf(xv, Wq[i * 2], a[0]);
        a[1] = fmaf(xv, Wq[i * 2 + 1], a[1]);
        a[2] = fmaf(xv, Wk[i * 2], a[2]);
        a[3] = fmaf(xv, Wk[i * 2 + 1], a[3]);
        a[4] = fmaf(xv, Wv[i * 2], a[4]);
        a[5] = fmaf(xv, Wv[i * 2 + 1], a[5]);
        a[6] = fmaf(xv, Ws[i * 2], a[6]);
        a[7] = fmaf(xv, Ws[i * 2 + 1], a[7]);
    }
#pragma unroll
    for (int i = 0; i < 8; i++) {
#pragma unroll
        for (int o = 16; o; o >>= 1) a[i] += __shfl_xor_sync(0xffffffffu, a[i], o);
    }
    if (lane == 0) {
        q[(size_t)node * 2 + 0] = a[0] + bq[0];
        q[(size_t)node * 2 + 1] = a[1] + bq[1];
        k[(size_t)node * 2 + 0] = a[2] + bk[0];
        k[(size_t)node * 2 + 1] = a[3] + bk[1];
        v[(size_t)node * 2 + 0] = a[4] + bv[0];
        v[(size_t)node * 2 + 1] = a[5] + bv[1];
        sOut[(size_t)node * 2 + 0] = a[6] + bs[0];
        sOut[(size_t)node * 2 + 1] = a[7] + bs[1];
    }
}

// ---------------- layer 3 fused finalize ----------------
__global__ void k_final3(const int* __restrict__ src,
                         const float* __restrict__ q2, const float* __restrict__ k2,
                         const float* __restrict__ v2, const float* __restrict__ s3,
                         float* __restrict__ out, int n, float scale) {
    int i = blockIdx.x * blockDim.x + threadIdx.x;
    if (i >= n) return;
    int s0 = g_rowptr[i], s1 = g_rowptr[i + 1];
    float q0 = q2[(size_t)i * 2 + 0], q1 = q2[(size_t)i * 2 + 1];
    float m = -INFINITY, den = 0.f, a0 = 0.f, a1 = 0.f;
    for (int j = s0; j < s1; j++) {
        int e = g_perm[j];
        int sv = src[e];
        float sc = (q0 * k2[(size_t)sv * 2] + q1 * k2[(size_t)sv * 2 + 1]) * scale;
        float nm = fmaxf(m, sc);
        float fa = __expf(m - nm);
        float w = __expf(sc - nm);
        den = den * fa + w;
        a0 = fmaf(w, v2[(size_t)sv * 2 + 0], a0 * fa);
        a1 = fmaf(w, v2[(size_t)sv * 2 + 1], a1 * fa);
        m = nm;
    }
    float inv = 1.f / (den + 1e-16f);
    a0 *= inv; a1 *= inv;
    float h0 = a0 + s3[(size_t)i * 2 + 0];
    float h1 = a1 + s3[(size_t)i * 2 + 1];
    float mx = fmaxf(h0, h1);
    float lse = mx + logf(expf(h0 - mx) + expf(h1 - mx));
    out[2 * i + 0] = h0 - lse;
    out[2 * i + 1] = h1 - lse;
}

// ---------------- launch ----------------
static inline int cdiv(int a, int b) { return (a + b - 1) / b; }

extern "C" void kernel_launch(void* const* d_in, const int* in_sizes, int n_in,
                              void* d_out, int out_size) {
    const float* x = (const float*)d_in[0];
    const int* ei = (const int*)d_in[1];
    const int N = in_sizes[0] / 128;
    const int E = in_sizes[1] / 2;
    const int* src = ei;
    const int* dst = ei + E;

    const float *Wq1 = (const float*)d_in[2],  *bq1 = (const float*)d_in[3];
    const float *Wk1 = (const float*)d_in[4],  *bk1 = (const float*)d_in[5];
    const float *Wv1 = (const float*)d_in[6],  *bv1 = (const float*)d_in[7];
    const float *Ws1 = (const float*)d_in[8],  *bs1 = (const float*)d_in[9];
    const float *Wq2 = (const float*)d_in[10], *bq2 = (const float*)d_in[11];
    const float *Wk2 = (const float*)d_in[12], *bk2 = (const float*)d_in[13];
    const float *Wv2 = (const float*)d_in[14], *bv2 = (const float*)d_in[15];
    const float *Ws2 = (const float*)d_in[16], *bs2 = (const float*)d_in[17];
    const float *Wq3 = (const float*)d_in[18], *bq3 = (const float*)d_in[19];
    const float *Wk3 = (const float*)d_in[20], *bk3 = (const float*)d_in[21];
    const float *Wv3 = (const float*)d_in[22], *bv3 = (const float*)d_in[23];
    const float *Ws3 = (const float*)d_in[24], *bs3 = (const float*)d_in[25];
    const float *ln1g = (const float*)d_in[26], *ln1b = (const float*)d_in[27];
    const float *ln2g = (const float*)d_in[28], *ln2b = (const float*)d_in[29];
    float* out = (float*)d_out;

    static float *yb = nullptr, *hb = nullptr;
    static bool cfg = false;
    static cudaStream_t s2;
    static cudaEvent_t evFork, evJoin;
    if (!cfg) {
        void* p;
        cudaGetSymbolAddress(&p, g_y); yb = (float*)p;
        cudaGetSymbolAddress(&p, g_h); hb = (float*)p;
        cudaStreamCreateWithFlags(&s2, cudaStreamNonBlocking);
        cudaEventCreateWithFlags(&evFork, cudaEventDisableTiming);
        cudaEventCreateWithFlags(&evJoin, cudaEventDisableTiming);
        cfg = true;
    }

    float* q = yb;
    float* sOut = yb + (size_t)NN * 512;
    __half* kh = (__half*)(yb + (size_t)NN * 1024);
    __half* vh = (__half*)(yb + (size_t)NN * 1280);
    float* q3 = yb + (size_t)NN * 1536;
    float* k3 = q3 + (size_t)NN * 2;
    float* v3 = k3 + (size_t)NN * 2;
    float* s3 = v3 + (size_t)NN * 2;

    const int TB = 256;

    // ---- fork: CSR build on s2, overlapped with layer-1 GEMM ----
    cudaEventRecord(evFork, 0);
    cudaStreamWaitEvent(s2, evFork, 0);

    int n1 = N + 1;
    int nch = cdiv(n1, 256);
    k_zero_rowptr<<<cdiv(n1, TB), TB, 0, s2>>>(n1);
    k_count<<<cdiv(E, TB), TB, 0, s2>>>(dst, E);
    k_block_sums<<<nch, 256, 0, s2>>>(n1);
    k_scan_chunks<<<1, 32, 0, s2>>>(nch);
    k_block_scan<<<nch, 256, 0, s2>>>(n1);
    k_cursor<<<cdiv(N, TB), TB, 0, s2>>>(N);
    k_scatter<<<cdiv(E, TB), TB, 0, s2>>>(dst, E);
    cudaEventRecord(evJoin, s2);

    // ================= layer 1: K=128, F=512, H=4, C=128 =================
    {
        int K = 128, F = 512;
        dim3 grid(4 * F / 128, cdiv(N, 128));
        k_mma4<<<grid, 256>>>(x, Wq1, bq1, q, Wk1, bk1, (float*)kh, Wv1, bv1, (float*)vh,
                              Ws1, bs1, sOut, N, K, F);
        cudaStreamWaitEvent(0, evJoin, 0);
        k_edge<4, 128><<<cdiv(N * 32, TB), TB>>>(src, q, kh, vh, sOut, ln1g, ln1b, hb, N,
                                                 0.08838834764831845f);
    }
    // ================= layer 2: K=512, F=256, H=4, C=64 =================
    {
        int K = 512, F = 256;
        dim3 grid(4 * F / 128, cdiv(N, 128));
        k_mma4<<<grid, 256>>>(hb, Wq2, bq2, q, Wk2, bk2, (float*)kh, Wv2, bv2, (float*)vh,
                              Ws2, bs2, sOut, N, K, F);
        k_edge<4, 64><<<cdiv(N * 32, TB), TB>>>(src, q, kh, vh, sOut, ln2g, ln2b, hb, N, 0.125f);
    }
    // ================= layer 3: K=256, F=2, H=1, C=2 =================
    {
        k_gemm3f<<<cdiv(N * 32, TB), TB>>>(hb, Wq3, bq3, Wk3, bk3, Wv3, bv3, Ws3, bs3,
                                           q3, k3, v3, s3, N);
        k_final3<<<cdiv(N, TB), TB>>>(src, q3, k3, v3, s3, out, N, 0.7071067811865475f);
    }
}